// round 3
// baseline (speedup 1.0000x reference)
#include <cuda_runtime.h>
#include <math.h>

// Problem constants
#define BB   4
#define CC   32
#define HH   64
#define WW   64
#define DD   288          // C*K*K
#define EE   144          // D/2
#define NHD  8            // heads
#define DHH  18           // head dim
#define SFN  4            // split factor
#define NTOK 4096         // H*W tokens per batch
#define NSEG 1024         // NTOK / SF
#define MTOT (BB*NTOK)    // 16384 tokens total

typedef unsigned long long ull;

// ---- packed f32x2 helpers (SASS FFMA2 etc., PTX-only) ----------------------
__device__ __forceinline__ ull pk2(float lo, float hi) {
    ull r; asm("mov.b64 %0,{%1,%2};" : "=l"(r) : "f"(lo), "f"(hi)); return r;
}
__device__ __forceinline__ void upk2(float& lo, float& hi, ull v) {
    asm("mov.b64 {%0,%1},%2;" : "=f"(lo), "=f"(hi) : "l"(v));
}
__device__ __forceinline__ ull fma2_(ull a, ull b, ull c) {
    ull d; asm("fma.rn.f32x2 %0,%1,%2,%3;" : "=l"(d) : "l"(a), "l"(b), "l"(c)); return d;
}
__device__ __forceinline__ ull add2_(ull a, ull b) {
    ull d; asm("add.rn.f32x2 %0,%1,%2;" : "=l"(d) : "l"(a), "l"(b)); return d;
}
__device__ __forceinline__ ull mul2_(ull a, ull b) {
    ull d; asm("mul.rn.f32x2 %0,%1,%2;" : "=l"(d) : "l"(a), "l"(b)); return d;
}

// Scratch (device globals: allocation-free rule)
__device__ float g_t[BB*CC*HH*WW];        // current image
__device__ float g_cols[MTOT*DD];         // unfold cols, token-major (m, d)
__device__ float g_colsn[MTOT*DD];        // layernormed cols
__device__ float g_xr[MTOT*EE];           // reduced tokens
__device__ float g_qkv[MTOT*3*EE];        // qkv
__device__ float g_o[MTOT*EE];            // attention output

// ---------------------------------------------------------------------------
// Fused unfold + LayerNorm(D). One block per token, 288 threads (one per d).
// ---------------------------------------------------------------------------
__global__ void unfold_ln_kernel(const float* __restrict__ img,
                                 const float* __restrict__ lng,
                                 const float* __restrict__ lnb)
{
    int tok = blockIdx.x;
    int b = tok / NTOK;
    int n = tok % NTOK;
    int h = n / WW, w = n % WW;
    int d = threadIdx.x;
    int c  = d / 9;
    int kh = (d % 9) / 3;
    int kw = d % 3;
    int hh = h + kh - 1, ww = w + kw - 1;
    float v = 0.f;
    if (hh >= 0 && hh < HH && ww >= 0 && ww < WW)
        v = img[((b*CC + c)*HH + hh)*WW + ww];

    float s = v, q = v * v;
    #pragma unroll
    for (int o = 16; o > 0; o >>= 1) {
        s += __shfl_down_sync(0xffffffffu, s, o);
        q += __shfl_down_sync(0xffffffffu, q, o);
    }
    __shared__ float ssum[9], ssq[9];
    __shared__ float s_mu, s_rstd;
    int wid = d >> 5, lid = d & 31;
    if (lid == 0) { ssum[wid] = s; ssq[wid] = q; }
    __syncthreads();
    if (d == 0) {
        float ts = 0.f, tq = 0.f;
        #pragma unroll
        for (int i = 0; i < 9; i++) { ts += ssum[i]; tq += ssq[i]; }
        float mu  = ts / (float)DD;
        float var = tq / (float)DD - mu * mu;
        s_mu   = mu;
        s_rstd = rsqrtf(var + 1e-5f);
    }
    __syncthreads();
    g_cols [tok*DD + d] = v;
    g_colsn[tok*DD + d] = (v - s_mu) * s_rstd * lng[d] + lnb[d];
}

// ---------------------------------------------------------------------------
// Tiled SGEMM v2 (packed f32x2): C(M,N) = A(M,K) * W(N,K)^T (+bias)(+resid).
// BM=64, BN=48, BK=16; 256 threads; each thread: 2 rows x 6 cols (3 f32x2).
// B tile stored transposed [BK][BN] so column pairs are natural LDS.64.
// ---------------------------------------------------------------------------
template<int K>
__global__ __launch_bounds__(256) void gemm_kernel(
    const float* __restrict__ A, const float* __restrict__ W,
    const float* __restrict__ bias, const float* resid,
    float* C, int Ncol)
{
    const int BM = 64, BN = 48, BK = 16;
    __shared__ float As[BM][BK + 1];
    __shared__ float Bs[BK][BN + 2];

    int tid = threadIdx.x;
    int ty = tid >> 3;          // 0..31 -> 2 rows each
    int tx = tid & 7;           // 0..7  -> 6 cols each (3 pairs)
    int row0 = blockIdx.y * BM;
    int col0 = blockIdx.x * BN;

    ull acc[2][3];
    #pragma unroll
    for (int r = 0; r < 2; r++)
        #pragma unroll
        for (int c = 0; c < 3; c++) acc[r][c] = 0ull;

    int ar = tid >> 2;             // 0..63
    int ak = (tid & 3) * 4;        // 0,4,8,12

    for (int kt = 0; kt < K; kt += BK) {
        float4 av = *reinterpret_cast<const float4*>(&A[(size_t)(row0 + ar)*K + kt + ak]);
        As[ar][ak+0] = av.x; As[ar][ak+1] = av.y;
        As[ar][ak+2] = av.z; As[ar][ak+3] = av.w;
        if (tid < 192) {
            float4 bv = *reinterpret_cast<const float4*>(&W[(size_t)(col0 + ar)*K + kt + ak]);
            Bs[ak+0][ar] = bv.x; Bs[ak+1][ar] = bv.y;
            Bs[ak+2][ar] = bv.z; Bs[ak+3][ar] = bv.w;
        }
        __syncthreads();
        #pragma unroll
        for (int kk = 0; kk < BK; kk++) {
            float a0 = As[ty*2 + 0][kk];
            float a1 = As[ty*2 + 1][kk];
            ull a0p = pk2(a0, a0);
            ull a1p = pk2(a1, a1);
            const ull* bp = reinterpret_cast<const ull*>(&Bs[kk][tx*6]);
            ull b0 = bp[0], b1 = bp[1], b2 = bp[2];
            acc[0][0] = fma2_(a0p, b0, acc[0][0]);
            acc[0][1] = fma2_(a0p, b1, acc[0][1]);
            acc[0][2] = fma2_(a0p, b2, acc[0][2]);
            acc[1][0] = fma2_(a1p, b0, acc[1][0]);
            acc[1][1] = fma2_(a1p, b1, acc[1][1]);
            acc[1][2] = fma2_(a1p, b2, acc[1][2]);
        }
        __syncthreads();
    }

    #pragma unroll
    for (int r = 0; r < 2; r++) {
        int row = row0 + ty*2 + r;
        #pragma unroll
        for (int c = 0; c < 3; c++) {
            int col = col0 + tx*6 + c*2;
            float lo, hi; upk2(lo, hi, acc[r][c]);
            if (bias)  { lo += bias[col]; hi += bias[col+1]; }
            if (resid) { lo += resid[(size_t)row*Ncol + col];
                         hi += resid[(size_t)row*Ncol + col + 1]; }
            float2 o; o.x = lo; o.y = hi;
            *reinterpret_cast<float2*>(&C[(size_t)row*Ncol + col]) = o;
        }
    }
}

// ---------------------------------------------------------------------------
// Attention v3 (packed f32x2): one CTA per (b, head, split), 512 threads,
// 2 queries per thread. K/V in smem, 40-float interleaved row pairs.
// d-dimension packed in f32x2 pairs (9 ulls per row).
// No online max (scores tiny, softmax shift-invariant) — validated r2.
// ---------------------------------------------------------------------------
#define KVSTR 40   // floats per (k,v) row pair: k at +0 (18 of 20), v at +20

__global__ __launch_bounds__(512) void attn_kernel()
{
    int seg  = blockIdx.x;                    // 0..127
    int b    = seg / (NHD * SFN);
    int rest = seg % (NHD * SFN);
    int hd   = rest / SFN;
    int sp   = rest % SFN;

    extern __shared__ float sm[];             // [NSEG][KVSTR]
    int base_tok = b * NTOK + sp * NSEG;
    const int QKVROW = 3 * EE;

    for (int idx = threadIdx.x; idx < NSEG * DHH; idx += 512) {
        int i = idx / DHH, d = idx % DHH;
        const float* row = &g_qkv[(size_t)(base_tok + i) * QKVROW + hd * DHH];
        sm[i*KVSTR + d]      = row[EE + d];       // K
        sm[i*KVSTR + 20 + d] = row[2*EE + d];     // V
    }
    __syncthreads();

    const float scale = 0.235702260395515841f;   // 18^-0.5
    ull scale2 = pk2(scale, scale);

    int qi = 2 * (int)threadIdx.x;               // 0..1022
    // (tok*432 + hd*18) is even -> 8B-aligned, safe as ull loads
    const ull* q0u = reinterpret_cast<const ull*>(
        &g_qkv[(size_t)(base_tok + qi) * QKVROW + hd * DHH]);
    const ull* q1u = reinterpret_cast<const ull*>(
        reinterpret_cast<const float*>(q0u) + QKVROW);

    ull qp0[9], qp1[9], acc0[9], acc1[9];
    #pragma unroll
    for (int i = 0; i < 9; i++) {
        qp0[i] = mul2_(q0u[i], scale2);
        qp1[i] = mul2_(q1u[i], scale2);
        acc0[i] = 0ull; acc1[i] = 0ull;
    }
    ull l2 = 0ull;                                // (0.f, 0.f)

    const float* kvf = sm;
    #pragma unroll 2
    for (int j = 0; j < NSEG; j++, kvf += KVSTR) {
        const ull* kvu = reinterpret_cast<const ull*>(kvf);
        ull s0 = 0ull, s1 = 0ull;
        #pragma unroll
        for (int i = 0; i < 9; i++) {
            ull kk = kvu[i];
            s0 = fma2_(qp0[i], kk, s0);
            s1 = fma2_(qp1[i], kk, s1);
        }
        float s0l, s0h, s1l, s1h;
        upk2(s0l, s0h, s0);
        upk2(s1l, s1h, s1);
        float p0 = __expf(s0l + s0h);
        float p1 = __expf(s1l + s1h);
        l2 = add2_(l2, pk2(p0, p1));
        ull p00 = pk2(p0, p0);
        ull p11 = pk2(p1, p1);
        const ull* vvu = kvu + 10;
        #pragma unroll
        for (int i = 0; i < 9; i++) {
            ull vv = vvu[i];
            acc0[i] = fma2_(p00, vv, acc0[i]);
            acc1[i] = fma2_(p11, vv, acc1[i]);
        }
    }

    float l0, l1; upk2(l0, l1, l2);
    ull r0 = pk2(1.f / l0, 1.f / l0);
    ull r1 = pk2(1.f / l1, 1.f / l1);
    // o offsets are even floats -> 8B-aligned
    ull* o0 = reinterpret_cast<ull*>(&g_o[(size_t)(base_tok + qi) * EE + hd * DHH]);
    ull* o1 = reinterpret_cast<ull*>(reinterpret_cast<float*>(o0) + EE);
    #pragma unroll
    for (int i = 0; i < 9; i++) {
        o0[i] = mul2_(acc0[i], r0);
        o1[i] = mul2_(acc1[i], r1);
    }
}

// ---------------------------------------------------------------------------
// Fold (gather form, no atomics)
// ---------------------------------------------------------------------------
__global__ void fold_kernel()
{
    int idx = blockIdx.x * blockDim.x + threadIdx.x;
    if (idx >= BB*CC*HH*WW) return;
    int w = idx % WW;
    int h = (idx / WW) % HH;
    int c = (idx / (WW*HH)) % CC;
    int b =  idx / (WW*HH*CC);
    float sum = 0.f;
    #pragma unroll
    for (int i = 0; i < 3; i++) {
        int hh = h + 1 - i;
        if (hh < 0 || hh >= HH) continue;
        #pragma unroll
        for (int j = 0; j < 3; j++) {
            int ww = w + 1 - j;
            if (ww < 0 || ww >= WW) continue;
            sum += g_cols[(size_t)(b*NTOK + hh*WW + ww)*DD + c*9 + i*3 + j];
        }
    }
    g_t[idx] = sum;
}

// ---------------------------------------------------------------------------
// Final: out = x + elu(conv3x3(t) + conv_b)
// ---------------------------------------------------------------------------
__global__ void conv_elu_kernel(const float* __restrict__ x,
                                const float* __restrict__ cw,
                                const float* __restrict__ cb,
                                float* __restrict__ out)
{
    int idx = blockIdx.x * blockDim.x + threadIdx.x;
    if (idx >= BB*CC*HH*WW) return;
    int w  = idx % WW;
    int h  = (idx / WW) % HH;
    int co = (idx / (WW*HH)) % CC;
    int b  =  idx / (WW*HH*CC);

    float sum = cb[co];
    for (int ci = 0; ci < CC; ci++) {
        const float* tplane = &g_t[((size_t)(b*CC + ci))*HH*WW];
        const float* wk = &cw[((size_t)(co*CC + ci))*9];
        #pragma unroll
        for (int kh = 0; kh < 3; kh++) {
            int hh = h + kh - 1;
            if (hh < 0 || hh >= HH) continue;
            #pragma unroll
            for (int kw = 0; kw < 3; kw++) {
                int ww = w + kw - 1;
                if (ww < 0 || ww >= WW) continue;
                sum = fmaf(tplane[hh*WW + ww], wk[kh*3 + kw], sum);
            }
        }
    }
    float e = sum > 0.f ? sum : expm1f(sum);
    out[idx] = x[idx] + e;
}

// ---------------------------------------------------------------------------
// Launch
// ---------------------------------------------------------------------------
extern "C" void kernel_launch(void* const* d_in, const int* in_sizes, int n_in,
                              void* d_out, int out_size)
{
    (void)in_sizes; (void)n_in; (void)out_size;
    const float* x     = (const float*)d_in[0];
    const float* ln_g  = (const float*)d_in[1];
    const float* ln_b  = (const float*)d_in[2];
    const float* convw = (const float*)d_in[3];
    const float* convb = (const float*)d_in[4];
    float* out = (float*)d_out;

    float *p_t, *p_cols, *p_colsn, *p_xr, *p_qkv, *p_o;
    cudaGetSymbolAddress((void**)&p_t,     g_t);
    cudaGetSymbolAddress((void**)&p_cols,  g_cols);
    cudaGetSymbolAddress((void**)&p_colsn, g_colsn);
    cudaGetSymbolAddress((void**)&p_xr,    g_xr);
    cudaGetSymbolAddress((void**)&p_qkv,   g_qkv);
    cudaGetSymbolAddress((void**)&p_o,     g_o);

    const int ATTN_SMEM = NSEG * KVSTR * (int)sizeof(float);   // 163840 B
    cudaFuncSetAttribute(attn_kernel, cudaFuncAttributeMaxDynamicSharedMemorySize, ATTN_SMEM);

    const int NPIX = BB*CC*HH*WW;

    for (int L = 0; L < 3; L++) {
        const float* wr   = (const float*)d_in[5 + 5*L + 0];
        const float* br   = (const float*)d_in[5 + 5*L + 1];
        const float* wqkv = (const float*)d_in[5 + 5*L + 2];
        const float* we   = (const float*)d_in[5 + 5*L + 3];
        const float* be   = (const float*)d_in[5 + 5*L + 4];
        const float* img  = (L == 0) ? x : p_t;

        unfold_ln_kernel<<<MTOT, 288>>>(img, ln_g, ln_b);
        gemm_kernel<288><<<dim3(3, MTOT/64), 256>>>(p_colsn, wr, br, nullptr, p_xr, 144);
        gemm_kernel<144><<<dim3(9, MTOT/64), 256>>>(p_xr, wqkv, nullptr, nullptr, p_qkv, 432);
        attn_kernel<<<BB*NHD*SFN, 512, ATTN_SMEM>>>();
        gemm_kernel<144><<<dim3(6, MTOT/64), 256>>>(p_o, we, be, p_cols, p_cols, 288);
        fold_kernel<<<(NPIX + 255)/256, 256>>>();
    }
    conv_elu_kernel<<<(NPIX + 255)/256, 256>>>(x, convw, convb, out);
}

// round 4
// speedup vs baseline: 1.0982x; 1.0982x over previous
#include <cuda_runtime.h>
#include <math.h>
#include <stdint.h>

// Problem constants
#define BB   4
#define CC   32
#define HH   64
#define WW   64
#define DD   288          // C*K*K
#define EE   144          // D/2
#define NHD  8            // heads
#define DHH  18           // head dim
#define SFN  4            // split factor
#define NTOK 4096         // H*W tokens per batch
#define NSEG 1024         // NTOK / SF
#define MTOT (BB*NTOK)    // 16384 tokens total

typedef unsigned long long ull;

// ---- packed f32x2 helpers ---------------------------------------------------
__device__ __forceinline__ ull pk2(float lo, float hi) {
    ull r; asm("mov.b64 %0,{%1,%2};" : "=l"(r) : "f"(lo), "f"(hi)); return r;
}
__device__ __forceinline__ void upk2(float& lo, float& hi, ull v) {
    asm("mov.b64 {%0,%1},%2;" : "=f"(lo), "=f"(hi) : "l"(v));
}
__device__ __forceinline__ ull fma2_(ull a, ull b, ull c) {
    ull d; asm("fma.rn.f32x2 %0,%1,%2,%3;" : "=l"(d) : "l"(a), "l"(b), "l"(c)); return d;
}
__device__ __forceinline__ ull add2_(ull a, ull b) {
    ull d; asm("add.rn.f32x2 %0,%1,%2;" : "=l"(d) : "l"(a), "l"(b)); return d;
}
__device__ __forceinline__ ull mul2_(ull a, ull b) {
    ull d; asm("mul.rn.f32x2 %0,%1,%2;" : "=l"(d) : "l"(a), "l"(b)); return d;
}

// ---- tf32 mma helpers -------------------------------------------------------
__device__ __forceinline__ uint32_t tf32r(float f) {
    uint32_t r; asm("cvt.rna.tf32.f32 %0,%1;" : "=r"(r) : "f"(f)); return r;
}
__device__ __forceinline__ void mma_tf32(float* d, const uint32_t* a, const uint32_t* b) {
    asm("mma.sync.aligned.m16n8k8.row.col.f32.tf32.tf32.f32 "
        "{%0,%1,%2,%3},{%4,%5,%6,%7},{%8,%9},{%0,%1,%2,%3};"
        : "+f"(d[0]), "+f"(d[1]), "+f"(d[2]), "+f"(d[3])
        : "r"(a[0]), "r"(a[1]), "r"(a[2]), "r"(a[3]), "r"(b[0]), "r"(b[1]));
}

// Scratch (device globals: allocation-free rule)
__device__ float g_t[BB*CC*HH*WW];        // current image
__device__ float g_cols[MTOT*DD];         // unfold cols, token-major (m, d)
__device__ float g_colsn[MTOT*DD];        // layernormed cols
__device__ float g_xr[MTOT*EE];           // reduced tokens
__device__ float g_qkv[MTOT*3*EE];        // qkv
__device__ float g_o[MTOT*EE];            // attention output

// ---------------------------------------------------------------------------
// Fused unfold + LayerNorm(D). One block per token, 288 threads.
// ---------------------------------------------------------------------------
__global__ void unfold_ln_kernel(const float* __restrict__ img,
                                 const float* __restrict__ lng,
                                 const float* __restrict__ lnb)
{
    int tok = blockIdx.x;
    int b = tok / NTOK;
    int n = tok % NTOK;
    int h = n / WW, w = n % WW;
    int d = threadIdx.x;
    int c  = d / 9;
    int kh = (d % 9) / 3;
    int kw = d % 3;
    int hh = h + kh - 1, ww = w + kw - 1;
    float v = 0.f;
    if (hh >= 0 && hh < HH && ww >= 0 && ww < WW)
        v = img[((b*CC + c)*HH + hh)*WW + ww];

    float s = v, q = v * v;
    #pragma unroll
    for (int o = 16; o > 0; o >>= 1) {
        s += __shfl_down_sync(0xffffffffu, s, o);
        q += __shfl_down_sync(0xffffffffu, q, o);
    }
    __shared__ float ssum[9], ssq[9];
    __shared__ float s_mu, s_rstd;
    int wid = d >> 5, lid = d & 31;
    if (lid == 0) { ssum[wid] = s; ssq[wid] = q; }
    __syncthreads();
    if (d == 0) {
        float ts = 0.f, tq = 0.f;
        #pragma unroll
        for (int i = 0; i < 9; i++) { ts += ssum[i]; tq += ssq[i]; }
        float mu  = ts / (float)DD;
        float var = tq / (float)DD - mu * mu;
        s_mu   = mu;
        s_rstd = rsqrtf(var + 1e-5f);
    }
    __syncthreads();
    g_cols [tok*DD + d] = v;
    g_colsn[tok*DD + d] = (v - s_mu) * s_rstd * lng[d] + lnb[d];
}

// ---------------------------------------------------------------------------
// GEMM via tensor cores (tf32 m16n8k8), gmem-direct (L1/L2 cached operands).
// C(M,N) = A(M,K) * W(N,K)^T (+bias)(+resid), all row-major.
// CTA: 128 threads = 4 warps stacked in M. Warp tile: 32(M) x 16(N)
//   = 2 m16 tiles x 2 n8 tiles. grid = (N/16, M/128).
// K % 8 == 0, N % 16 == 0, M % 128 == 0 hold for all three GEMMs.
// ---------------------------------------------------------------------------
template<int K>
__global__ __launch_bounds__(128) void gemm_mma_kernel(
    const float* __restrict__ A, const float* __restrict__ W,
    const float* __restrict__ bias, const float* resid,
    float* __restrict__ C, int Ncol)
{
    int warp = threadIdx.x >> 5;
    int lane = threadIdx.x & 31;
    int g = lane >> 2;          // group 0..7
    int t = lane & 3;           // thread-in-group 0..3

    int row0 = blockIdx.y * 128 + warp * 32;   // warp's first M row
    int col0 = blockIdx.x * 16;                // warp's first N col

    float d[2][2][4];
    #pragma unroll
    for (int mt = 0; mt < 2; mt++)
        #pragma unroll
        for (int nt = 0; nt < 2; nt++)
            #pragma unroll
            for (int i = 0; i < 4; i++) d[mt][nt][i] = 0.f;

    // base pointers for this lane
    const float* aP = A + (size_t)(row0 + g) * K + t;     // (row0+g, t)
    const float* bP = W + (size_t)(col0 + g) * K + t;     // (col0+g, t)

    #pragma unroll 2
    for (int kt = 0; kt < K; kt += 8) {
        uint32_t a[2][4], bfr[2][2];
        #pragma unroll
        for (int mt = 0; mt < 2; mt++) {
            const float* p = aP + (size_t)mt * 16 * K + kt;
            a[mt][0] = tf32r(p[0]);
            a[mt][1] = tf32r(p[(size_t)8 * K]);
            a[mt][2] = tf32r(p[4]);
            a[mt][3] = tf32r(p[(size_t)8 * K + 4]);
        }
        #pragma unroll
        for (int nt = 0; nt < 2; nt++) {
            const float* p = bP + (size_t)nt * 8 * K + kt;
            bfr[nt][0] = tf32r(p[0]);
            bfr[nt][1] = tf32r(p[4]);
        }
        #pragma unroll
        for (int mt = 0; mt < 2; mt++)
            #pragma unroll
            for (int nt = 0; nt < 2; nt++)
                mma_tf32(d[mt][nt], a[mt], bfr[nt]);
    }

    // epilogue: c0:(g,2t) c1:(g,2t+1) c2:(g+8,2t) c3:(g+8,2t+1)
    #pragma unroll
    for (int mt = 0; mt < 2; mt++) {
        int r0 = row0 + mt * 16 + g;
        int r1 = r0 + 8;
        #pragma unroll
        for (int nt = 0; nt < 2; nt++) {
            int cc = col0 + nt * 8 + 2 * t;
            float v0 = d[mt][nt][0], v1 = d[mt][nt][1];
            float v2 = d[mt][nt][2], v3 = d[mt][nt][3];
            if (bias) {
                float b0 = bias[cc], b1 = bias[cc + 1];
                v0 += b0; v1 += b1; v2 += b0; v3 += b1;
            }
            if (resid) {
                const float2 u0 = *reinterpret_cast<const float2*>(&resid[(size_t)r0*Ncol + cc]);
                const float2 u1 = *reinterpret_cast<const float2*>(&resid[(size_t)r1*Ncol + cc]);
                v0 += u0.x; v1 += u0.y; v2 += u1.x; v3 += u1.y;
            }
            float2 o0; o0.x = v0; o0.y = v1;
            float2 o1; o1.x = v2; o1.y = v3;
            *reinterpret_cast<float2*>(&C[(size_t)r0*Ncol + cc]) = o0;
            *reinterpret_cast<float2*>(&C[(size_t)r1*Ncol + cc]) = o1;
        }
    }
}

// ---------------------------------------------------------------------------
// Attention v3 (packed f32x2): one CTA per (b, head, split), 512 threads,
// 2 queries per thread. K/V in smem, 40-float interleaved row pairs.
// No online max (scores tiny, softmax shift-invariant) — validated r2.
// ---------------------------------------------------------------------------
#define KVSTR 40

__global__ __launch_bounds__(512) void attn_kernel()
{
    int seg  = blockIdx.x;
    int b    = seg / (NHD * SFN);
    int rest = seg % (NHD * SFN);
    int hd   = rest / SFN;
    int sp   = rest % SFN;

    extern __shared__ float sm[];             // [NSEG][KVSTR]
    int base_tok = b * NTOK + sp * NSEG;
    const int QKVROW = 3 * EE;

    for (int idx = threadIdx.x; idx < NSEG * DHH; idx += 512) {
        int i = idx / DHH, d = idx % DHH;
        const float* row = &g_qkv[(size_t)(base_tok + i) * QKVROW + hd * DHH];
        sm[i*KVSTR + d]      = row[EE + d];       // K
        sm[i*KVSTR + 20 + d] = row[2*EE + d];     // V
    }
    __syncthreads();

    const float scale = 0.235702260395515841f;   // 18^-0.5
    ull scale2 = pk2(scale, scale);

    int qi = 2 * (int)threadIdx.x;
    const ull* q0u = reinterpret_cast<const ull*>(
        &g_qkv[(size_t)(base_tok + qi) * QKVROW + hd * DHH]);
    const ull* q1u = reinterpret_cast<const ull*>(
        reinterpret_cast<const float*>(q0u) + QKVROW);

    ull qp0[9], qp1[9], acc0[9], acc1[9];
    #pragma unroll
    for (int i = 0; i < 9; i++) {
        qp0[i] = mul2_(q0u[i], scale2);
        qp1[i] = mul2_(q1u[i], scale2);
        acc0[i] = 0ull; acc1[i] = 0ull;
    }
    ull l2 = 0ull;

    const float* kvf = sm;
    #pragma unroll 2
    for (int j = 0; j < NSEG; j++, kvf += KVSTR) {
        const ull* kvu = reinterpret_cast<const ull*>(kvf);
        ull s0 = 0ull, s1 = 0ull;
        #pragma unroll
        for (int i = 0; i < 9; i++) {
            ull kk = kvu[i];
            s0 = fma2_(qp0[i], kk, s0);
            s1 = fma2_(qp1[i], kk, s1);
        }
        float s0l, s0h, s1l, s1h;
        upk2(s0l, s0h, s0);
        upk2(s1l, s1h, s1);
        float p0 = __expf(s0l + s0h);
        float p1 = __expf(s1l + s1h);
        l2 = add2_(l2, pk2(p0, p1));
        ull p00 = pk2(p0, p0);
        ull p11 = pk2(p1, p1);
        const ull* vvu = kvu + 10;
        #pragma unroll
        for (int i = 0; i < 9; i++) {
            ull vv = vvu[i];
            acc0[i] = fma2_(p00, vv, acc0[i]);
            acc1[i] = fma2_(p11, vv, acc1[i]);
        }
    }

    float l0, l1; upk2(l0, l1, l2);
    ull r0 = pk2(1.f / l0, 1.f / l0);
    ull r1 = pk2(1.f / l1, 1.f / l1);
    ull* o0 = reinterpret_cast<ull*>(&g_o[(size_t)(base_tok + qi) * EE + hd * DHH]);
    ull* o1 = reinterpret_cast<ull*>(reinterpret_cast<float*>(o0) + EE);
    #pragma unroll
    for (int i = 0; i < 9; i++) {
        o0[i] = mul2_(acc0[i], r0);
        o1[i] = mul2_(acc1[i], r1);
    }
}

// ---------------------------------------------------------------------------
// Fold (gather form, no atomics)
// ---------------------------------------------------------------------------
__global__ void fold_kernel()
{
    int idx = blockIdx.x * blockDim.x + threadIdx.x;
    if (idx >= BB*CC*HH*WW) return;
    int w = idx % WW;
    int h = (idx / WW) % HH;
    int c = (idx / (WW*HH)) % CC;
    int b =  idx / (WW*HH*CC);
    float sum = 0.f;
    #pragma unroll
    for (int i = 0; i < 3; i++) {
        int hh = h + 1 - i;
        if (hh < 0 || hh >= HH) continue;
        #pragma unroll
        for (int j = 0; j < 3; j++) {
            int ww = w + 1 - j;
            if (ww < 0 || ww >= WW) continue;
            sum += g_cols[(size_t)(b*NTOK + hh*WW + ww)*DD + c*9 + i*3 + j];
        }
    }
    g_t[idx] = sum;
}

// ---------------------------------------------------------------------------
// Final: out = x + elu(conv3x3(t) + conv_b)
// ---------------------------------------------------------------------------
__global__ void conv_elu_kernel(const float* __restrict__ x,
                                const float* __restrict__ cw,
                                const float* __restrict__ cb,
                                float* __restrict__ out)
{
    int idx = blockIdx.x * blockDim.x + threadIdx.x;
    if (idx >= BB*CC*HH*WW) return;
    int w  = idx % WW;
    int h  = (idx / WW) % HH;
    int co = (idx / (WW*HH)) % CC;
    int b  =  idx / (WW*HH*CC);

    float sum = cb[co];
    for (int ci = 0; ci < CC; ci++) {
        const float* tplane = &g_t[((size_t)(b*CC + ci))*HH*WW];
        const float* wk = &cw[((size_t)(co*CC + ci))*9];
        #pragma unroll
        for (int kh = 0; kh < 3; kh++) {
            int hh = h + kh - 1;
            if (hh < 0 || hh >= HH) continue;
            #pragma unroll
            for (int kw = 0; kw < 3; kw++) {
                int ww = w + kw - 1;
                if (ww < 0 || ww >= WW) continue;
                sum = fmaf(tplane[hh*WW + ww], wk[kh*3 + kw], sum);
            }
        }
    }
    float e = sum > 0.f ? sum : expm1f(sum);
    out[idx] = x[idx] + e;
}

// ---------------------------------------------------------------------------
// Launch
// ---------------------------------------------------------------------------
extern "C" void kernel_launch(void* const* d_in, const int* in_sizes, int n_in,
                              void* d_out, int out_size)
{
    (void)in_sizes; (void)n_in; (void)out_size;
    const float* x     = (const float*)d_in[0];
    const float* ln_g  = (const float*)d_in[1];
    const float* ln_b  = (const float*)d_in[2];
    const float* convw = (const float*)d_in[3];
    const float* convb = (const float*)d_in[4];
    float* out = (float*)d_out;

    float *p_t, *p_cols, *p_colsn, *p_xr, *p_qkv, *p_o;
    cudaGetSymbolAddress((void**)&p_t,     g_t);
    cudaGetSymbolAddress((void**)&p_cols,  g_cols);
    cudaGetSymbolAddress((void**)&p_colsn, g_colsn);
    cudaGetSymbolAddress((void**)&p_xr,    g_xr);
    cudaGetSymbolAddress((void**)&p_qkv,   g_qkv);
    cudaGetSymbolAddress((void**)&p_o,     g_o);

    const int ATTN_SMEM = NSEG * KVSTR * (int)sizeof(float);   // 163840 B
    cudaFuncSetAttribute(attn_kernel, cudaFuncAttributeMaxDynamicSharedMemorySize, ATTN_SMEM);

    const int NPIX = BB*CC*HH*WW;

    for (int L = 0; L < 3; L++) {
        const float* wr   = (const float*)d_in[5 + 5*L + 0];
        const float* br   = (const float*)d_in[5 + 5*L + 1];
        const float* wqkv = (const float*)d_in[5 + 5*L + 2];
        const float* we   = (const float*)d_in[5 + 5*L + 3];
        const float* be   = (const float*)d_in[5 + 5*L + 4];
        const float* img  = (L == 0) ? x : p_t;

        unfold_ln_kernel<<<MTOT, 288>>>(img, ln_g, ln_b);
        // xr = colsn @ wr^T + br        (16384x288)*(144x288)^T
        gemm_mma_kernel<288><<<dim3(144/16, MTOT/128), 128>>>(p_colsn, wr, br, nullptr, p_xr, 144);
        // qkv = xr @ wqkv^T             (16384x144)*(432x144)^T
        gemm_mma_kernel<144><<<dim3(432/16, MTOT/128), 128>>>(p_xr, wqkv, nullptr, nullptr, p_qkv, 432);
        attn_kernel<<<BB*NHD*SFN, 512, ATTN_SMEM>>>();
        // cols += o @ we^T + be         (16384x144)*(288x144)^T, residual in-place
        gemm_mma_kernel<144><<<dim3(288/16, MTOT/128), 128>>>(p_o, we, be, p_cols, p_cols, 288);
        fold_kernel<<<(NPIX + 255)/256, 256>>>();
    }
    conv_elu_kernel<<<(NPIX + 255)/256, 256>>>(x, convw, convb, out);
}

// round 5
// speedup vs baseline: 1.7448x; 1.5888x over previous
#include <cuda_runtime.h>
#include <cuda_bf16.h>
#include <math.h>
#include <stdint.h>

// Problem constants
#define BB   4
#define CC   32
#define HH   64
#define WW   64
#define DD   288          // C*K*K
#define EE   144          // D/2
#define NHD  8            // heads
#define DHH  18           // head dim
#define SFN  4            // split factor
#define NTOK 4096         // H*W tokens per batch
#define NSEG 1024         // NTOK / SF
#define MTOT (BB*NTOK)    // 16384 tokens total

// ---- tf32 mma helpers -------------------------------------------------------
__device__ __forceinline__ uint32_t tf32r(float f) {
    uint32_t r; asm("cvt.rna.tf32.f32 %0,%1;" : "=r"(r) : "f"(f)); return r;
}
__device__ __forceinline__ void mma_tf32(float* d, const uint32_t* a, const uint32_t* b) {
    asm("mma.sync.aligned.m16n8k8.row.col.f32.tf32.tf32.f32 "
        "{%0,%1,%2,%3},{%4,%5,%6,%7},{%8,%9},{%0,%1,%2,%3};"
        : "+f"(d[0]), "+f"(d[1]), "+f"(d[2]), "+f"(d[3])
        : "r"(a[0]), "r"(a[1]), "r"(a[2]), "r"(a[3]), "r"(b[0]), "r"(b[1]));
}

// ---- bf16 mma helpers -------------------------------------------------------
__device__ __forceinline__ void mma_bf16(float* c, const uint32_t* a, uint32_t b0, uint32_t b1) {
    asm("mma.sync.aligned.m16n8k16.row.col.f32.bf16.bf16.f32 "
        "{%0,%1,%2,%3},{%4,%5,%6,%7},{%8,%9},{%0,%1,%2,%3};"
        : "+f"(c[0]), "+f"(c[1]), "+f"(c[2]), "+f"(c[3])
        : "r"(a[0]), "r"(a[1]), "r"(a[2]), "r"(a[3]), "r"(b0), "r"(b1));
}
__device__ __forceinline__ float ex2f(float x) {
    float y; asm("ex2.approx.f32 %0,%1;" : "=f"(y) : "f"(x)); return y;
}
__device__ __forceinline__ uint32_t packbf(float lo, float hi) {
    __nv_bfloat162 h = __floats2bfloat162_rn(lo, hi);   // .x = lo half, .y = hi half
    return *reinterpret_cast<uint32_t*>(&h);
}
__device__ __forceinline__ uint32_t lds32(const __nv_bfloat16* p) {
    return *reinterpret_cast<const uint32_t*>(p);
}

// Scratch (device globals: allocation-free rule)
__device__ float g_t[BB*CC*HH*WW];        // current image
__device__ float g_cols[MTOT*DD];         // unfold cols, token-major (m, d)
__device__ float g_colsn[MTOT*DD];        // layernormed cols
__device__ float g_xr[MTOT*EE];           // reduced tokens
__device__ float g_qkv[MTOT*3*EE];        // qkv
__device__ float g_o[MTOT*EE];            // attention output

// ---------------------------------------------------------------------------
// Fused unfold + LayerNorm(D). One WARP per token (pure shfl reduction).
// 256 threads = 8 tokens per CTA; 9 elements per lane.
// ---------------------------------------------------------------------------
__global__ __launch_bounds__(256) void unfold_ln_kernel(
    const float* __restrict__ img,
    const float* __restrict__ lng,
    const float* __restrict__ lnb)
{
    int warp = threadIdx.x >> 5, lane = threadIdx.x & 31;
    int tok = blockIdx.x * 8 + warp;
    int b = tok / NTOK;
    int n = tok % NTOK;
    int h = n / WW, w = n % WW;

    float v[9];
    float s = 0.f, q = 0.f;
    #pragma unroll
    for (int i = 0; i < 9; i++) {
        int d = i * 32 + lane;          // < 288
        int c  = d / 9;
        int r  = d - c * 9;
        int kh = r / 3, kw = r - kh * 3;
        int hh = h + kh - 1, ww = w + kw - 1;
        float x = 0.f;
        if (hh >= 0 && hh < HH && ww >= 0 && ww < WW)
            x = img[((b*CC + c)*HH + hh)*WW + ww];
        v[i] = x; s += x; q = fmaf(x, x, q);
    }
    #pragma unroll
    for (int o = 16; o > 0; o >>= 1) {
        s += __shfl_xor_sync(0xffffffffu, s, o);
        q += __shfl_xor_sync(0xffffffffu, q, o);
    }
    float mu = s * (1.f / DD);
    float rstd = rsqrtf(q * (1.f / DD) - mu * mu + 1e-5f);
    #pragma unroll
    for (int i = 0; i < 9; i++) {
        int d = i * 32 + lane;
        g_cols [ (size_t)tok*DD + d] = v[i];
        g_colsn[ (size_t)tok*DD + d] = (v[i] - mu) * rstd * __ldg(&lng[d]) + __ldg(&lnb[d]);
    }
}

// ---------------------------------------------------------------------------
// GEMM via tensor cores (tf32 m16n8k8), gmem-direct.
// C(M,N) = A(M,K) * W(N,K)^T (+bias)(+resid), all row-major.
// ---------------------------------------------------------------------------
template<int K>
__global__ __launch_bounds__(128) void gemm_mma_kernel(
    const float* __restrict__ A, const float* __restrict__ W,
    const float* __restrict__ bias, const float* resid,
    float* __restrict__ C, int Ncol)
{
    int warp = threadIdx.x >> 5;
    int lane = threadIdx.x & 31;
    int g = lane >> 2;
    int t = lane & 3;

    int row0 = blockIdx.y * 128 + warp * 32;
    int col0 = blockIdx.x * 16;

    float d[2][2][4];
    #pragma unroll
    for (int mt = 0; mt < 2; mt++)
        #pragma unroll
        for (int nt = 0; nt < 2; nt++)
            #pragma unroll
            for (int i = 0; i < 4; i++) d[mt][nt][i] = 0.f;

    const float* aP = A + (size_t)(row0 + g) * K + t;
    const float* bP = W + (size_t)(col0 + g) * K + t;

    #pragma unroll 2
    for (int kt = 0; kt < K; kt += 8) {
        uint32_t a[2][4], bfr[2][2];
        #pragma unroll
        for (int mt = 0; mt < 2; mt++) {
            const float* p = aP + (size_t)mt * 16 * K + kt;
            a[mt][0] = tf32r(p[0]);
            a[mt][1] = tf32r(p[(size_t)8 * K]);
            a[mt][2] = tf32r(p[4]);
            a[mt][3] = tf32r(p[(size_t)8 * K + 4]);
        }
        #pragma unroll
        for (int nt = 0; nt < 2; nt++) {
            const float* p = bP + (size_t)nt * 8 * K + kt;
            bfr[nt][0] = tf32r(p[0]);
            bfr[nt][1] = tf32r(p[4]);
        }
        #pragma unroll
        for (int mt = 0; mt < 2; mt++)
            #pragma unroll
            for (int nt = 0; nt < 2; nt++)
                mma_tf32(d[mt][nt], a[mt], bfr[nt]);
    }

    #pragma unroll
    for (int mt = 0; mt < 2; mt++) {
        int r0 = row0 + mt * 16 + g;
        int r1 = r0 + 8;
        #pragma unroll
        for (int nt = 0; nt < 2; nt++) {
            int cc = col0 + nt * 8 + 2 * t;
            float v0 = d[mt][nt][0], v1 = d[mt][nt][1];
            float v2 = d[mt][nt][2], v3 = d[mt][nt][3];
            if (bias) {
                float b0 = bias[cc], b1 = bias[cc + 1];
                v0 += b0; v1 += b1; v2 += b0; v3 += b1;
            }
            if (resid) {
                const float2 u0 = *reinterpret_cast<const float2*>(&resid[(size_t)r0*Ncol + cc]);
                const float2 u1 = *reinterpret_cast<const float2*>(&resid[(size_t)r1*Ncol + cc]);
                v0 += u0.x; v1 += u0.y; v2 += u1.x; v3 += u1.y;
            }
            float2 o0; o0.x = v0; o0.y = v1;
            float2 o1; o1.x = v2; o1.y = v3;
            *reinterpret_cast<float2*>(&C[(size_t)r0*Ncol + cc]) = o0;
            *reinterpret_cast<float2*>(&C[(size_t)r1*Ncol + cc]) = o1;
        }
    }
}

// ---------------------------------------------------------------------------
// Attention v4: bf16 tensor-core flash attention.
// One CTA per (b, head, split) segment (128 CTAs), 512 threads = 16 warps.
// K staged bf16 [1024][KPITCH=40] (d padded 18->32 zeros), V staged transposed
// bf16 [24][VPITCH=1032]. Each warp processes 4 q-tiles of 16 queries over the
// full 1024 keys in j-tiles of 16:
//   S (2x m16n8, tf-free bf16 QK mma) -> ex2 -> bf16x2 pack == A-frag of PV mma.
// No online max (scores tiny; softmax shift-invariant) — validated r2-r4.
// log2(e)*scale folded into Q so exp == single ex2.
// ---------------------------------------------------------------------------
#define KPITCH 40
#define VPITCH 1032
#define ATTN_SMEM_BYTES (NSEG*KPITCH*2 + 24*VPITCH*2)   // 81920 + 49536 = 131456

__global__ __launch_bounds__(512) void attn_kernel()
{
    int seg  = blockIdx.x;
    int b    = seg / (NHD * SFN);
    int rest = seg % (NHD * SFN);
    int hd   = rest / SFN;
    int sp   = rest % SFN;
    int base = b * NTOK + sp * NSEG;
    const int QKVROW = 3 * EE;

    extern __shared__ __nv_bfloat16 smb[];
    __nv_bfloat16* Ks = smb;                     // [NSEG][KPITCH]
    __nv_bfloat16* Vt = smb + NSEG * KPITCH;     // [24][VPITCH]

    // stage K (bf16, zero-pad d to KPITCH)
    for (int idx = threadIdx.x; idx < NSEG * KPITCH; idx += 512) {
        int i = idx / KPITCH, d = idx - i * KPITCH;
        float x = (d < DHH) ? g_qkv[(size_t)(base + i) * QKVROW + EE + hd * DHH + d] : 0.f;
        Ks[idx] = __float2bfloat16(x);
    }
    // stage V^T (bf16): Vt[d][j] = V[j][d], d rows 18..23 zero
    for (int idx = threadIdx.x; idx < NSEG * 24; idx += 512) {
        int d = idx / NSEG, j = idx - d * NSEG;
        float x = (d < DHH) ? g_qkv[(size_t)(base + j) * QKVROW + 2 * EE + hd * DHH + d] : 0.f;
        Vt[d * VPITCH + j] = __float2bfloat16(x);
    }
    __syncthreads();

    int lane = threadIdx.x & 31, warp = threadIdx.x >> 5;
    int g = lane >> 2, t = lane & 3;
    const float qs = 0.235702260395515841f * 1.4426950408889634f;  // 18^-0.5 * log2(e)

    for (int qt = warp; qt < NSEG / 16; qt += 16) {
        int q0 = qt * 16;
        const float* Qb = &g_qkv[(size_t)(base + q0) * QKVROW + hd * DHH];
        const float* r0 = Qb + (size_t)g * QKVROW;
        const float* r1 = Qb + (size_t)(g + 8) * QKVROW;

        uint32_t qa[2][4];
        {
            float2 x;
            x = *(const float2*)(r0 + 2*t);     qa[0][0] = packbf(x.x*qs, x.y*qs);
            x = *(const float2*)(r1 + 2*t);     qa[0][1] = packbf(x.x*qs, x.y*qs);
            x = *(const float2*)(r0 + 2*t + 8); qa[0][2] = packbf(x.x*qs, x.y*qs);
            x = *(const float2*)(r1 + 2*t + 8); qa[0][3] = packbf(x.x*qs, x.y*qs);
            if (t == 0) {
                x = *(const float2*)(r0 + 16);  qa[1][0] = packbf(x.x*qs, x.y*qs);
                x = *(const float2*)(r1 + 16);  qa[1][1] = packbf(x.x*qs, x.y*qs);
            } else { qa[1][0] = 0u; qa[1][1] = 0u; }
            qa[1][2] = 0u; qa[1][3] = 0u;
        }

        float o[3][4];
        #pragma unroll
        for (int dn = 0; dn < 3; dn++)
            #pragma unroll
            for (int i = 0; i < 4; i++) o[dn][i] = 0.f;
        float lg = 0.f, lg8 = 0.f;

        for (int j0 = 0; j0 < NSEG; j0 += 16) {
            const __nv_bfloat16* kr0 = Ks + (size_t)(j0 + g) * KPITCH;
            const __nv_bfloat16* kr1 = kr0 + 8 * KPITCH;
            float s0[4] = {0.f,0.f,0.f,0.f};
            float s1[4] = {0.f,0.f,0.f,0.f};
            // QK: kstep 0 (d 0..15)
            mma_bf16(s0, qa[0], lds32(kr0 + 2*t), lds32(kr0 + 2*t + 8));
            mma_bf16(s1, qa[0], lds32(kr1 + 2*t), lds32(kr1 + 2*t + 8));
            // QK: kstep 1 (d 16..31; only d16,17 nonzero)
            mma_bf16(s0, qa[1], lds32(kr0 + 16 + 2*t), lds32(kr0 + 24 + 2*t));
            mma_bf16(s1, qa[1], lds32(kr1 + 16 + 2*t), lds32(kr1 + 24 + 2*t));

            float e00 = ex2f(s0[0]), e01 = ex2f(s0[1]), e02 = ex2f(s0[2]), e03 = ex2f(s0[3]);
            float e10 = ex2f(s1[0]), e11 = ex2f(s1[1]), e12 = ex2f(s1[2]), e13 = ex2f(s1[3]);
            lg  += e00 + e01 + e10 + e11;
            lg8 += e02 + e03 + e12 + e13;

            uint32_t pa[4];
            pa[0] = packbf(e00, e01);   // {P[g][j0+2t], P[g][j0+2t+1]}
            pa[1] = packbf(e02, e03);   // row g+8
            pa[2] = packbf(e10, e11);   // cols j0+8+2t
            pa[3] = packbf(e12, e13);

            #pragma unroll
            for (int dn = 0; dn < 3; dn++) {
                const __nv_bfloat16* vr = Vt + (size_t)(dn*8 + g) * VPITCH + j0;
                mma_bf16(o[dn], pa, lds32(vr + 2*t), lds32(vr + 2*t + 8));
            }
        }

        lg  += __shfl_xor_sync(0xffffffffu, lg, 1);
        lg  += __shfl_xor_sync(0xffffffffu, lg, 2);
        lg8 += __shfl_xor_sync(0xffffffffu, lg8, 1);
        lg8 += __shfl_xor_sync(0xffffffffu, lg8, 2);
        float ig = 1.f / lg, ig8 = 1.f / lg8;

        #pragma unroll
        for (int dn = 0; dn < 3; dn++) {
            int dc = dn * 8 + 2 * t;
            if (dc < DHH) {   // dn<2 always; dn==2 only t==0 (cols 16,17)
                float2 u0; u0.x = o[dn][0] * ig;  u0.y = o[dn][1] * ig;
                float2 u1; u1.x = o[dn][2] * ig8; u1.y = o[dn][3] * ig8;
                *reinterpret_cast<float2*>(&g_o[(size_t)(base + q0 + g)     * EE + hd*DHH + dc]) = u0;
                *reinterpret_cast<float2*>(&g_o[(size_t)(base + q0 + g + 8) * EE + hd*DHH + dc]) = u1;
            }
        }
    }
}

// ---------------------------------------------------------------------------
// Fold (gather form, no atomics)
// ---------------------------------------------------------------------------
__global__ void fold_kernel()
{
    int idx = blockIdx.x * blockDim.x + threadIdx.x;
    if (idx >= BB*CC*HH*WW) return;
    int w = idx % WW;
    int h = (idx / WW) % HH;
    int c = (idx / (WW*HH)) % CC;
    int b =  idx / (WW*HH*CC);
    float sum = 0.f;
    #pragma unroll
    for (int i = 0; i < 3; i++) {
        int hh = h + 1 - i;
        if (hh < 0 || hh >= HH) continue;
        #pragma unroll
        for (int j = 0; j < 3; j++) {
            int ww = w + 1 - j;
            if (ww < 0 || ww >= WW) continue;
            sum += g_cols[(size_t)(b*NTOK + hh*WW + ww)*DD + c*9 + i*3 + j];
        }
    }
    g_t[idx] = sum;
}

// ---------------------------------------------------------------------------
// Final: out = x + elu(conv3x3(t) + conv_b)
// ---------------------------------------------------------------------------
__global__ void conv_elu_kernel(const float* __restrict__ x,
                                const float* __restrict__ cw,
                                const float* __restrict__ cb,
                                float* __restrict__ out)
{
    int idx = blockIdx.x * blockDim.x + threadIdx.x;
    if (idx >= BB*CC*HH*WW) return;
    int w  = idx % WW;
    int h  = (idx / WW) % HH;
    int co = (idx / (WW*HH)) % CC;
    int b  =  idx / (WW*HH*CC);

    float sum = cb[co];
    for (int ci = 0; ci < CC; ci++) {
        const float* tplane = &g_t[((size_t)(b*CC + ci))*HH*WW];
        const float* wk = &cw[((size_t)(co*CC + ci))*9];
        #pragma unroll
        for (int kh = 0; kh < 3; kh++) {
            int hh = h + kh - 1;
            if (hh < 0 || hh >= HH) continue;
            #pragma unroll
            for (int kw = 0; kw < 3; kw++) {
                int ww = w + kw - 1;
                if (ww < 0 || ww >= WW) continue;
                sum = fmaf(tplane[hh*WW + ww], wk[kh*3 + kw], sum);
            }
        }
    }
    float e = sum > 0.f ? sum : expm1f(sum);
    out[idx] = x[idx] + e;
}

// ---------------------------------------------------------------------------
// Launch
// ---------------------------------------------------------------------------
extern "C" void kernel_launch(void* const* d_in, const int* in_sizes, int n_in,
                              void* d_out, int out_size)
{
    (void)in_sizes; (void)n_in; (void)out_size;
    const float* x     = (const float*)d_in[0];
    const float* ln_g  = (const float*)d_in[1];
    const float* ln_b  = (const float*)d_in[2];
    const float* convw = (const float*)d_in[3];
    const float* convb = (const float*)d_in[4];
    float* out = (float*)d_out;

    float *p_t, *p_cols, *p_colsn, *p_xr, *p_qkv, *p_o;
    cudaGetSymbolAddress((void**)&p_t,     g_t);
    cudaGetSymbolAddress((void**)&p_cols,  g_cols);
    cudaGetSymbolAddress((void**)&p_colsn, g_colsn);
    cudaGetSymbolAddress((void**)&p_xr,    g_xr);
    cudaGetSymbolAddress((void**)&p_qkv,   g_qkv);
    cudaGetSymbolAddress((void**)&p_o,     g_o);

    cudaFuncSetAttribute(attn_kernel, cudaFuncAttributeMaxDynamicSharedMemorySize, ATTN_SMEM_BYTES);

    const int NPIX = BB*CC*HH*WW;

    for (int L = 0; L < 3; L++) {
        const float* wr   = (const float*)d_in[5 + 5*L + 0];
        const float* br   = (const float*)d_in[5 + 5*L + 1];
        const float* wqkv = (const float*)d_in[5 + 5*L + 2];
        const float* we   = (const float*)d_in[5 + 5*L + 3];
        const float* be   = (const float*)d_in[5 + 5*L + 4];
        const float* img  = (L == 0) ? x : p_t;

        unfold_ln_kernel<<<MTOT/8, 256>>>(img, ln_g, ln_b);
        gemm_mma_kernel<288><<<dim3(144/16, MTOT/128), 128>>>(p_colsn, wr, br, nullptr, p_xr, 144);
        gemm_mma_kernel<144><<<dim3(432/16, MTOT/128), 128>>>(p_xr, wqkv, nullptr, nullptr, p_qkv, 432);
        attn_kernel<<<BB*NHD*SFN, 512, ATTN_SMEM_BYTES>>>();
        gemm_mma_kernel<144><<<dim3(288/16, MTOT/128), 128>>>(p_o, we, be, p_cols, p_cols, 288);
        fold_kernel<<<(NPIX + 255)/256, 256>>>();
    }
    conv_elu_kernel<<<(NPIX + 255)/256, 256>>>(x, convw, convb, out);
}

// round 6
// speedup vs baseline: 2.7373x; 1.5688x over previous
#include <cuda_runtime.h>
#include <cuda_bf16.h>
#include <math.h>
#include <stdint.h>

// Problem constants
#define BB   4
#define CC   32
#define HH   64
#define WW   64
#define DD   288          // C*K*K
#define EE   144          // D/2
#define NHD  8            // heads
#define DHH  18           // head dim
#define SFN  4            // split factor
#define NTOK 4096         // H*W tokens per batch
#define NSEG 1024         // NTOK / SF
#define MTOT (BB*NTOK)    // 16384 tokens total

// weight buffer layout (bf16), per layer
#define WR_ELEMS   (EE*DD)          // 41472
#define WQKV_ELEMS (3*EE*EE)        // 62208
#define WE_ELEMS   (DD*EE)          // 41472
#define WL_STRIDE  (WR_ELEMS + WQKV_ELEMS + WE_ELEMS)   // 145152
#define WQKV_OFF   WR_ELEMS
#define WE_OFF     (WR_ELEMS + WQKV_ELEMS)

// ---- bf16 mma helpers -------------------------------------------------------
__device__ __forceinline__ void mma_bf16(float* c, const uint32_t* a, uint32_t b0, uint32_t b1) {
    asm("mma.sync.aligned.m16n8k16.row.col.f32.bf16.bf16.f32 "
        "{%0,%1,%2,%3},{%4,%5,%6,%7},{%8,%9},{%0,%1,%2,%3};"
        : "+f"(c[0]), "+f"(c[1]), "+f"(c[2]), "+f"(c[3])
        : "r"(a[0]), "r"(a[1]), "r"(a[2]), "r"(a[3]), "r"(b0), "r"(b1));
}
__device__ __forceinline__ float ex2f(float x) {
    float y; asm("ex2.approx.f32 %0,%1;" : "=f"(y) : "f"(x)); return y;
}
__device__ __forceinline__ uint32_t packbf(float lo, float hi) {
    __nv_bfloat162 h = __floats2bfloat162_rn(lo, hi);
    return *reinterpret_cast<uint32_t*>(&h);
}
__device__ __forceinline__ uint32_t ld32bf(const __nv_bfloat16* p) {
    return *reinterpret_cast<const uint32_t*>(p);
}

// Scratch (device globals: allocation-free rule)
__device__ float         g_t[BB*CC*HH*WW];       // current image (fp32)
__device__ float         g_cols[MTOT*DD];        // unfold cols fp32 (residual stream)
__device__ __nv_bfloat16 g_colsn_bf[MTOT*DD];    // layernormed cols (bf16)
__device__ __nv_bfloat16 g_xr_bf[MTOT*EE];       // reduced tokens (bf16)
__device__ __nv_bfloat16 g_qkv_bf[MTOT*3*EE];    // qkv (bf16, Q pre-scaled)
__device__ __nv_bfloat16 g_o_bf[MTOT*EE];        // attention output (bf16)
__device__ __nv_bfloat16 g_w_bf[3*WL_STRIDE];    // converted weights, 3 layers

// ---------------------------------------------------------------------------
// Weight conversion (fp32 -> bf16), one layer per launch.
// Q-rows of wqkv are pre-scaled by 18^-0.5 * log2(e).
// ---------------------------------------------------------------------------
__global__ void wconv_kernel(const float* __restrict__ wr,
                             const float* __restrict__ wqkv,
                             const float* __restrict__ we,
                             __nv_bfloat16* __restrict__ dst)
{
    const float qs = 0.235702260395515841f * 1.4426950408889634f;
    int i = blockIdx.x * 256 + threadIdx.x;
    if (i >= WL_STRIDE) return;
    float v;
    if (i < WR_ELEMS) {
        v = wr[i];
    } else if (i < WE_OFF) {
        int j = i - WQKV_OFF;
        v = wqkv[j];
        if (j < EE * EE) v *= qs;        // rows 0..143 (Q), row-major (3E,E)
    } else {
        v = we[i - WE_OFF];
    }
    dst[i] = __float2bfloat16(v);
}

// ---------------------------------------------------------------------------
// Fused unfold + LayerNorm(D). One WARP per token; bf16 normalized output.
// ---------------------------------------------------------------------------
__global__ __launch_bounds__(256) void unfold_ln_kernel(
    const float* __restrict__ img,
    const float* __restrict__ lng,
    const float* __restrict__ lnb)
{
    int warp = threadIdx.x >> 5, lane = threadIdx.x & 31;
    int tok = blockIdx.x * 8 + warp;
    int b = tok / NTOK;
    int n = tok % NTOK;
    int h = n / WW, w = n % WW;

    float v[9];
    float s = 0.f, q = 0.f;
    #pragma unroll
    for (int i = 0; i < 9; i++) {
        int d = i * 32 + lane;
        int c  = d / 9;
        int r  = d - c * 9;
        int kh = r / 3, kw = r - kh * 3;
        int hh = h + kh - 1, ww = w + kw - 1;
        float x = 0.f;
        if (hh >= 0 && hh < HH && ww >= 0 && ww < WW)
            x = img[((b*CC + c)*HH + hh)*WW + ww];
        v[i] = x; s += x; q = fmaf(x, x, q);
    }
    #pragma unroll
    for (int o = 16; o > 0; o >>= 1) {
        s += __shfl_xor_sync(0xffffffffu, s, o);
        q += __shfl_xor_sync(0xffffffffu, q, o);
    }
    float mu = s * (1.f / DD);
    float rstd = rsqrtf(q * (1.f / DD) - mu * mu + 1e-5f);
    #pragma unroll
    for (int i = 0; i < 9; i++) {
        int d = i * 32 + lane;
        g_cols[(size_t)tok*DD + d] = v[i];
        g_colsn_bf[(size_t)tok*DD + d] =
            __float2bfloat16((v[i] - mu) * rstd * __ldg(&lng[d]) + __ldg(&lnb[d]));
    }
}

// ---------------------------------------------------------------------------
// bf16 tensor-core GEMM, gmem-direct: C(M,N) = A(M,K) * W(N,K)^T (+bias)(+res)
// CTA: 128 thr = 4 warps stacked in M; warp tile 32x16 (2 m16 x 2 n8).
// BOUT: true -> bf16 packed output, false -> fp32 output with residual add.
// ---------------------------------------------------------------------------
template<int K, bool BOUT>
__global__ __launch_bounds__(128) void gemm_bf16_kernel(
    const __nv_bfloat16* __restrict__ A, const __nv_bfloat16* __restrict__ W,
    const float* __restrict__ bias, const float* __restrict__ resid,
    void* __restrict__ Cout, int Ncol)
{
    int warp = threadIdx.x >> 5;
    int lane = threadIdx.x & 31;
    int g = lane >> 2;
    int t = lane & 3;

    int row0 = blockIdx.y * 128 + warp * 32;
    int col0 = blockIdx.x * 16;

    float d[2][2][4];
    #pragma unroll
    for (int mt = 0; mt < 2; mt++)
        #pragma unroll
        for (int nt = 0; nt < 2; nt++)
            #pragma unroll
            for (int i = 0; i < 4; i++) d[mt][nt][i] = 0.f;

    const __nv_bfloat16* aP = A + (size_t)(row0 + g) * K + 2 * t;
    const __nv_bfloat16* bP = W + (size_t)(col0 + g) * K + 2 * t;

    #pragma unroll 2
    for (int kt = 0; kt < K; kt += 16) {
        uint32_t a[2][4], bf[2][2];
        #pragma unroll
        for (int mt = 0; mt < 2; mt++) {
            const __nv_bfloat16* p = aP + (size_t)mt * 16 * K + kt;
            a[mt][0] = ld32bf(p);
            a[mt][1] = ld32bf(p + (size_t)8 * K);
            a[mt][2] = ld32bf(p + 8);
            a[mt][3] = ld32bf(p + (size_t)8 * K + 8);
        }
        #pragma unroll
        for (int nt = 0; nt < 2; nt++) {
            const __nv_bfloat16* p = bP + (size_t)nt * 8 * K + kt;
            bf[nt][0] = ld32bf(p);
            bf[nt][1] = ld32bf(p + 8);
        }
        #pragma unroll
        for (int mt = 0; mt < 2; mt++)
            #pragma unroll
            for (int nt = 0; nt < 2; nt++)
                mma_bf16(d[mt][nt], a[mt], bf[nt][0], bf[nt][1]);
    }

    #pragma unroll
    for (int mt = 0; mt < 2; mt++) {
        int r0 = row0 + mt * 16 + g;
        int r1 = r0 + 8;
        #pragma unroll
        for (int nt = 0; nt < 2; nt++) {
            int cc = col0 + nt * 8 + 2 * t;
            float v0 = d[mt][nt][0], v1 = d[mt][nt][1];
            float v2 = d[mt][nt][2], v3 = d[mt][nt][3];
            if (bias) {
                float b0 = bias[cc], b1 = bias[cc + 1];
                v0 += b0; v1 += b1; v2 += b0; v3 += b1;
            }
            if (BOUT) {
                uint32_t* C = (uint32_t*)Cout;
                C[((size_t)r0 * Ncol + cc) >> 1] = packbf(v0, v1);
                C[((size_t)r1 * Ncol + cc) >> 1] = packbf(v2, v3);
            } else {
                float* C = (float*)Cout;
                if (resid) {
                    const float2 u0 = *reinterpret_cast<const float2*>(&resid[(size_t)r0*Ncol + cc]);
                    const float2 u1 = *reinterpret_cast<const float2*>(&resid[(size_t)r1*Ncol + cc]);
                    v0 += u0.x; v1 += u0.y; v2 += u1.x; v3 += u1.y;
                }
                float2 o0; o0.x = v0; o0.y = v1;
                float2 o1; o1.x = v2; o1.y = v3;
                *reinterpret_cast<float2*>(&C[(size_t)r0*Ncol + cc]) = o0;
                *reinterpret_cast<float2*>(&C[(size_t)r1*Ncol + cc]) = o1;
            }
        }
    }
}

// ---------------------------------------------------------------------------
// Attention v5: bf16 flash attention, bf16 qkv input (Q pre-scaled in weights).
// One CTA per (b, head, split), 512 threads = 16 warps.
// K staged [1024][KPITCH=40] bf16 (u32 copies); V^T staged [24][VPITCH=1032].
// S -> ex2 -> bf16x2 pack == PV A-fragment; no shuffles, no online max.
// ---------------------------------------------------------------------------
#define KPITCH 40
#define VPITCH 1032
#define ATTN_SMEM_BYTES (NSEG*KPITCH*2 + 24*VPITCH*2)   // 131456

__global__ __launch_bounds__(512) void attn_kernel()
{
    int seg  = blockIdx.x;
    int b    = seg / (NHD * SFN);
    int rest = seg % (NHD * SFN);
    int hd   = rest / SFN;
    int sp   = rest % SFN;
    int base = b * NTOK + sp * NSEG;
    const int QKVROW = 3 * EE;

    extern __shared__ __nv_bfloat16 smb[];
    __nv_bfloat16* Ks = smb;                     // [NSEG][KPITCH]
    __nv_bfloat16* Vt = smb + NSEG * KPITCH;     // [24][VPITCH]

    const uint32_t* qk32 = reinterpret_cast<const uint32_t*>(g_qkv_bf);
    uint32_t* Ks32 = reinterpret_cast<uint32_t*>(Ks);

    // stage K: u32 copies, rows padded 9 -> 20 u32
    for (int idx = threadIdx.x; idx < NSEG * (KPITCH/2); idx += 512) {
        int i = idx / (KPITCH/2), d2 = idx - i * (KPITCH/2);
        uint32_t v = 0u;
        if (d2 < 9)
            v = qk32[(((size_t)(base + i) * QKVROW + EE + hd * DHH) >> 1) + d2];
        Ks32[i * (KPITCH/2) + d2] = v;
    }
    // stage V^T: Vt[d][j] = V[j][d]
    for (int idx = threadIdx.x; idx < NSEG * 24; idx += 512) {
        int dd = idx >> 10, j = idx & (NSEG - 1);
        __nv_bfloat16 v = __float2bfloat16(0.f);
        if (dd < DHH)
            v = g_qkv_bf[(size_t)(base + j) * QKVROW + 2 * EE + hd * DHH + dd];
        Vt[dd * VPITCH + j] = v;
    }
    __syncthreads();

    int lane = threadIdx.x & 31, warp = threadIdx.x >> 5;
    int g = lane >> 2, t = lane & 3;

    for (int qt = warp; qt < NSEG / 16; qt += 16) {
        int q0 = qt * 16;
        const uint32_t* q32a = qk32 + (((size_t)(base + q0 + g)     * QKVROW + hd * DHH) >> 1);
        const uint32_t* q32b = qk32 + (((size_t)(base + q0 + g + 8) * QKVROW + hd * DHH) >> 1);

        uint32_t qa[2][4];
        qa[0][0] = q32a[t];
        qa[0][1] = q32b[t];
        qa[0][2] = q32a[t + 4];
        qa[0][3] = q32b[t + 4];
        qa[1][0] = (t == 0) ? q32a[8] : 0u;
        qa[1][1] = (t == 0) ? q32b[8] : 0u;
        qa[1][2] = 0u; qa[1][3] = 0u;

        float o[3][4];
        #pragma unroll
        for (int dn = 0; dn < 3; dn++)
            #pragma unroll
            for (int i = 0; i < 4; i++) o[dn][i] = 0.f;
        float lg = 0.f, lg8 = 0.f;

        for (int j0 = 0; j0 < NSEG; j0 += 16) {
            const __nv_bfloat16* kr0 = Ks + (size_t)(j0 + g) * KPITCH;
            const __nv_bfloat16* kr1 = kr0 + 8 * KPITCH;
            float s0[4] = {0.f,0.f,0.f,0.f};
            float s1[4] = {0.f,0.f,0.f,0.f};
            mma_bf16(s0, qa[0], ld32bf(kr0 + 2*t), ld32bf(kr0 + 2*t + 8));
            mma_bf16(s1, qa[0], ld32bf(kr1 + 2*t), ld32bf(kr1 + 2*t + 8));
            mma_bf16(s0, qa[1], ld32bf(kr0 + 16 + 2*t), ld32bf(kr0 + 24 + 2*t));
            mma_bf16(s1, qa[1], ld32bf(kr1 + 16 + 2*t), ld32bf(kr1 + 24 + 2*t));

            float e00 = ex2f(s0[0]), e01 = ex2f(s0[1]), e02 = ex2f(s0[2]), e03 = ex2f(s0[3]);
            float e10 = ex2f(s1[0]), e11 = ex2f(s1[1]), e12 = ex2f(s1[2]), e13 = ex2f(s1[3]);
            lg  += e00 + e01 + e10 + e11;
            lg8 += e02 + e03 + e12 + e13;

            uint32_t pa[4];
            pa[0] = packbf(e00, e01);
            pa[1] = packbf(e02, e03);
            pa[2] = packbf(e10, e11);
            pa[3] = packbf(e12, e13);

            #pragma unroll
            for (int dn = 0; dn < 3; dn++) {
                const __nv_bfloat16* vr = Vt + (size_t)(dn*8 + g) * VPITCH + j0;
                mma_bf16(o[dn], pa, ld32bf(vr + 2*t), ld32bf(vr + 2*t + 8));
            }
        }

        lg  += __shfl_xor_sync(0xffffffffu, lg, 1);
        lg  += __shfl_xor_sync(0xffffffffu, lg, 2);
        lg8 += __shfl_xor_sync(0xffffffffu, lg8, 1);
        lg8 += __shfl_xor_sync(0xffffffffu, lg8, 2);
        float ig = 1.f / lg, ig8 = 1.f / lg8;

        uint32_t* o32 = reinterpret_cast<uint32_t*>(g_o_bf);
        #pragma unroll
        for (int dn = 0; dn < 3; dn++) {
            int dc = dn * 8 + 2 * t;
            if (dc < DHH) {
                o32[((size_t)(base + q0 + g)     * EE + hd*DHH + dc) >> 1] = packbf(o[dn][0]*ig,  o[dn][1]*ig);
                o32[((size_t)(base + q0 + g + 8) * EE + hd*DHH + dc) >> 1] = packbf(o[dn][2]*ig8, o[dn][3]*ig8);
            }
        }
    }
}

// ---------------------------------------------------------------------------
// Fold (gather form, no atomics)
// ---------------------------------------------------------------------------
__global__ void fold_kernel()
{
    int idx = blockIdx.x * blockDim.x + threadIdx.x;
    if (idx >= BB*CC*HH*WW) return;
    int w = idx % WW;
    int h = (idx / WW) % HH;
    int c = (idx / (WW*HH)) % CC;
    int b =  idx / (WW*HH*CC);
    float sum = 0.f;
    #pragma unroll
    for (int i = 0; i < 3; i++) {
        int hh = h + 1 - i;
        if (hh < 0 || hh >= HH) continue;
        #pragma unroll
        for (int j = 0; j < 3; j++) {
            int ww = w + 1 - j;
            if (ww < 0 || ww >= WW) continue;
            sum += g_cols[(size_t)(b*NTOK + hh*WW + ww)*DD + c*9 + i*3 + j];
        }
    }
    g_t[idx] = sum;
}

// ---------------------------------------------------------------------------
// Final: out = x + elu(conv3x3(t) + conv_b)
// ---------------------------------------------------------------------------
__global__ void conv_elu_kernel(const float* __restrict__ x,
                                const float* __restrict__ cw,
                                const float* __restrict__ cb,
                                float* __restrict__ out)
{
    int idx = blockIdx.x * blockDim.x + threadIdx.x;
    if (idx >= BB*CC*HH*WW) return;
    int w  = idx % WW;
    int h  = (idx / WW) % HH;
    int co = (idx / (WW*HH)) % CC;
    int b  =  idx / (WW*HH*CC);

    float sum = cb[co];
    for (int ci = 0; ci < CC; ci++) {
        const float* tplane = &g_t[((size_t)(b*CC + ci))*HH*WW];
        const float* wk = &cw[((size_t)(co*CC + ci))*9];
        #pragma unroll
        for (int kh = 0; kh < 3; kh++) {
            int hh = h + kh - 1;
            if (hh < 0 || hh >= HH) continue;
            #pragma unroll
            for (int kw = 0; kw < 3; kw++) {
                int ww = w + kw - 1;
                if (ww < 0 || ww >= WW) continue;
                sum = fmaf(tplane[hh*WW + ww], wk[kh*3 + kw], sum);
            }
        }
    }
    float e = sum > 0.f ? sum : expm1f(sum);
    out[idx] = x[idx] + e;
}

// ---------------------------------------------------------------------------
// Launch
// ---------------------------------------------------------------------------
extern "C" void kernel_launch(void* const* d_in, const int* in_sizes, int n_in,
                              void* d_out, int out_size)
{
    (void)in_sizes; (void)n_in; (void)out_size;
    const float* x     = (const float*)d_in[0];
    const float* ln_g  = (const float*)d_in[1];
    const float* ln_b  = (const float*)d_in[2];
    const float* convw = (const float*)d_in[3];
    const float* convb = (const float*)d_in[4];
    float* out = (float*)d_out;

    float *p_t, *p_cols;
    __nv_bfloat16 *p_colsn, *p_xr, *p_qkv, *p_o, *p_w;
    cudaGetSymbolAddress((void**)&p_t,     g_t);
    cudaGetSymbolAddress((void**)&p_cols,  g_cols);
    cudaGetSymbolAddress((void**)&p_colsn, g_colsn_bf);
    cudaGetSymbolAddress((void**)&p_xr,    g_xr_bf);
    cudaGetSymbolAddress((void**)&p_qkv,   g_qkv_bf);
    cudaGetSymbolAddress((void**)&p_o,     g_o_bf);
    cudaGetSymbolAddress((void**)&p_w,     g_w_bf);

    cudaFuncSetAttribute(attn_kernel, cudaFuncAttributeMaxDynamicSharedMemorySize, ATTN_SMEM_BYTES);

    const int NPIX = BB*CC*HH*WW;

    // convert all weights up front
    for (int L = 0; L < 3; L++) {
        wconv_kernel<<<(WL_STRIDE + 255)/256, 256>>>(
            (const float*)d_in[5 + 5*L + 0],
            (const float*)d_in[5 + 5*L + 2],
            (const float*)d_in[5 + 5*L + 3],
            p_w + (size_t)L * WL_STRIDE);
    }

    for (int L = 0; L < 3; L++) {
        const float* br = (const float*)d_in[5 + 5*L + 1];
        const float* be = (const float*)d_in[5 + 5*L + 4];
        const __nv_bfloat16* wr   = p_w + (size_t)L * WL_STRIDE;
        const __nv_bfloat16* wqkv = wr + WQKV_OFF;
        const __nv_bfloat16* we   = wr + WE_OFF;
        const float* img = (L == 0) ? x : p_t;

        unfold_ln_kernel<<<MTOT/8, 256>>>(img, ln_g, ln_b);
        // xr = colsn @ wr^T + br   (bf16 out)
        gemm_bf16_kernel<288, true><<<dim3(EE/16, MTOT/128), 128>>>(
            p_colsn, wr, br, nullptr, p_xr, EE);
        // qkv = xr @ wqkv^T        (bf16 out, Q rows pre-scaled)
        gemm_bf16_kernel<144, true><<<dim3(3*EE/16, MTOT/128), 128>>>(
            p_xr, wqkv, nullptr, nullptr, p_qkv, 3*EE);
        attn_kernel<<<BB*NHD*SFN, 512, ATTN_SMEM_BYTES>>>();
        // cols += o @ we^T + be    (fp32 out + residual)
        gemm_bf16_kernel<144, false><<<dim3(DD/16, MTOT/128), 128>>>(
            p_o, we, be, p_cols, p_cols, DD);
        fold_kernel<<<(NPIX + 255)/256, 256>>>();
    }
    conv_elu_kernel<<<(NPIX + 255)/256, 256>>>(x, convw, convb, out);
}

// round 7
// speedup vs baseline: 3.8550x; 1.4084x over previous
#include <cuda_runtime.h>
#include <cuda_fp16.h>
#include <math.h>
#include <stdint.h>

// Problem constants
#define BB   4
#define CC   32
#define HH   64
#define WW   64
#define DD   288          // C*K*K
#define EE   144          // D/2
#define NHD  8            // heads
#define DHH  18           // head dim
#define SFN  4            // split factor
#define NTOK 4096         // H*W tokens per batch
#define NSEG 1024         // NTOK / SF
#define MTOT (BB*NTOK)    // 16384 tokens total

// weight buffer layout (f16), per layer
#define WR_ELEMS   (EE*DD)
#define WQKV_ELEMS (3*EE*EE)
#define WE_ELEMS   (DD*EE)
#define WL_STRIDE  (WR_ELEMS + WQKV_ELEMS + WE_ELEMS)
#define WQKV_OFF   WR_ELEMS
#define WE_OFF     (WR_ELEMS + WQKV_ELEMS)

// ---- f16 mma / ldmatrix helpers --------------------------------------------
__device__ __forceinline__ void mma_f16(float* c, const uint32_t* a, uint32_t b0, uint32_t b1) {
    asm("mma.sync.aligned.m16n8k16.row.col.f32.f16.f16.f32 "
        "{%0,%1,%2,%3},{%4,%5,%6,%7},{%8,%9},{%0,%1,%2,%3};"
        : "+f"(c[0]), "+f"(c[1]), "+f"(c[2]), "+f"(c[3])
        : "r"(a[0]), "r"(a[1]), "r"(a[2]), "r"(a[3]), "r"(b0), "r"(b1));
}
__device__ __forceinline__ void ldsm_x4(uint32_t* r, uint32_t addr) {
    asm volatile("ldmatrix.sync.aligned.m8n8.x4.shared.b16 {%0,%1,%2,%3},[%4];"
        : "=r"(r[0]), "=r"(r[1]), "=r"(r[2]), "=r"(r[3]) : "r"(addr));
}
__device__ __forceinline__ void ldsm_x2(uint32_t* r, uint32_t addr) {
    asm volatile("ldmatrix.sync.aligned.m8n8.x2.shared.b16 {%0,%1},[%2];"
        : "=r"(r[0]), "=r"(r[1]) : "r"(addr));
}
__device__ __forceinline__ void ldsm_x2t(uint32_t* r, uint32_t addr) {
    asm volatile("ldmatrix.sync.aligned.m8n8.x2.trans.shared.b16 {%0,%1},[%2];"
        : "=r"(r[0]), "=r"(r[1]) : "r"(addr));
}
// pack two f32 -> f16x2 register  (d.hi = first src, d.lo = second src)
__device__ __forceinline__ uint32_t cvth2(float lo, float hi) {
    uint32_t r; asm("cvt.rn.f16x2.f32 %0,%1,%2;" : "=r"(r) : "f"(hi), "f"(lo)); return r;
}
__device__ __forceinline__ uint32_t ex2h2(uint32_t x) {
    uint32_t r; asm("ex2.approx.f16x2 %0,%1;" : "=r"(r) : "r"(x)); return r;
}
__device__ __forceinline__ uint32_t packh2(float lo, float hi) {
    __half2 h = __floats2half2_rn(lo, hi);
    return *reinterpret_cast<uint32_t*>(&h);
}

// Scratch (device globals: allocation-free rule)
__device__ float  g_t[BB*CC*HH*WW];        // current image (fp32)
__device__ float  g_cols[DD*MTOT];         // unfold cols fp32, D-MAJOR [d][tok]
__device__ __half g_colsn_h[MTOT*DD];      // layernormed cols (f16, tok-major)
__device__ __half g_xr_h[MTOT*EE];         // reduced tokens (f16)
__device__ __half g_qkv_h[MTOT*3*EE];      // qkv (f16, Q pre-scaled)
__device__ __half g_o_h[MTOT*EE];          // attention output (f16)
__device__ __half g_w_h[3*WL_STRIDE];      // converted weights, 3 layers

// ---------------------------------------------------------------------------
// Weight conversion fp32 -> f16; Q-rows of wqkv pre-scaled by 18^-0.5*log2(e).
// ---------------------------------------------------------------------------
__global__ void wconv_kernel(const float* __restrict__ wr,
                             const float* __restrict__ wqkv,
                             const float* __restrict__ we,
                             __half* __restrict__ dst)
{
    const float qs = 0.235702260395515841f * 1.4426950408889634f;
    int i = blockIdx.x * 256 + threadIdx.x;
    if (i >= WL_STRIDE) return;
    float v;
    if (i < WR_ELEMS) v = wr[i];
    else if (i < WE_OFF) {
        int j = i - WQKV_OFF;
        v = wqkv[j];
        if (j < EE * EE) v *= qs;
    } else v = we[i - WE_OFF];
    dst[i] = __float2half(v);
}

// ---------------------------------------------------------------------------
// unfold + LayerNorm v2: one CTA per 32 w-contiguous tokens, smem img patch.
// Writes g_cols (fp32, d-major) and g_colsn_h (f16, tok-major).
// ---------------------------------------------------------------------------
__global__ __launch_bounds__(256) void unfold_ln_kernel(
    const float* __restrict__ img,
    const float* __restrict__ lng,
    const float* __restrict__ lnb)
{
    int t0 = blockIdx.x * 32;
    int b = t0 / NTOK, n = t0 % NTOK;
    int h = n / WW, w0 = n % WW;          // w0 in {0,32}

    __shared__ float patch[CC][3][34];
    __shared__ float red[8][33], redq[8][33];
    __shared__ float s_mu[32], s_rs[32];

    for (int idx = threadIdx.x; idx < CC*3*34; idx += 256) {
        int c = idx / 102, rem = idx - c*102;
        int r = rem / 34, wc = rem - r*34;
        int hh = h - 1 + r, ww = w0 - 1 + wc;
        float v = 0.f;
        if (hh >= 0 && hh < HH && ww >= 0 && ww < WW)
            v = img[((b*CC + c)*HH + hh)*WW + ww];
        patch[c][r][wc] = v;
    }
    __syncthreads();

    int tl = threadIdx.x & 31, slice = threadIdx.x >> 5;
    float s = 0.f, q = 0.f;
    #pragma unroll
    for (int i = 0; i < 36; i++) {
        int d = slice * 36 + i;
        int c = d / 9, k = d - c*9, kh = k/3, kw = k - kh*3;
        float v = patch[c][kh][tl + kw];
        s += v; q = fmaf(v, v, q);
    }
    red[slice][tl] = s; redq[slice][tl] = q;
    __syncthreads();
    if (threadIdx.x < 32) {
        float ts = 0.f, tq = 0.f;
        #pragma unroll
        for (int i = 0; i < 8; i++) { ts += red[i][threadIdx.x]; tq += redq[i][threadIdx.x]; }
        float mu = ts * (1.f/DD);
        s_mu[threadIdx.x] = mu;
        s_rs[threadIdx.x] = rsqrtf(tq * (1.f/DD) - mu*mu + 1e-5f);
    }
    __syncthreads();

    // cols fp32, d-major: coalesced over tokens
    for (int idx = threadIdx.x; idx < DD*32; idx += 256) {
        int d = idx >> 5, t = idx & 31;
        int c = d / 9, k = d - c*9, kh = k/3, kw = k - kh*3;
        g_cols[(size_t)d*MTOT + t0 + t] = patch[c][kh][t + kw];
    }
    // colsn f16, tok-major: coalesced over d (packed pairs)
    uint32_t* cn32 = reinterpret_cast<uint32_t*>(g_colsn_h);
    for (int idx = threadIdx.x; idx < 32*(DD/2); idx += 256) {
        int t = idx / (DD/2), d2 = idx - t*(DD/2);
        int d0 = 2*d2, d1 = d0 + 1;
        int c0 = d0/9, k0 = d0 - c0*9;
        int c1 = d1/9, k1 = d1 - c1*9;
        float v0 = patch[c0][k0/3][t + k0%3];
        float v1 = patch[c1][k1/3][t + k1%3];
        float mu = s_mu[t], rs = s_rs[t];
        v0 = (v0 - mu)*rs*lng[d0] + lnb[d0];
        v1 = (v1 - mu)*rs*lng[d1] + lnb[d1];
        cn32[((size_t)(t0+t)*DD + d0) >> 1] = packh2(v0, v1);
    }
}

// ---------------------------------------------------------------------------
// f16 GEMM, smem-staged + ldmatrix: C(M,N) = A(M,K)*W(N,K)^T (+bias)(+resid)
// CTA 256 thr = 8 warps (4M x 2N); CTA tile 128x48; warp tile 32x24; k-chunk 48.
// BOUT=true: f16 packed tok-major out. BOUT=false: fp32 D-MAJOR out + resid.
// ---------------------------------------------------------------------------
#define APITCH 56
template<int K, bool BOUT>
__global__ __launch_bounds__(256) void gemm_h_kernel(
    const __half* __restrict__ A, const __half* __restrict__ W,
    const float* __restrict__ bias, const float* __restrict__ resid,
    void* __restrict__ Cout, int Ncol)
{
    __shared__ __half As[128*APITCH];
    __shared__ __half Bs[48*APITCH];

    int tid = threadIdx.x;
    int warp = tid >> 5, lane = tid & 31;
    int g = lane >> 2, t = lane & 3;
    int wm = warp & 3, wn = warp >> 2;
    int rowB = blockIdx.y * 128;
    int colB = blockIdx.x * 48;

    float acc[2][3][4];
    #pragma unroll
    for (int i = 0; i < 2; i++)
        #pragma unroll
        for (int j = 0; j < 3; j++)
            #pragma unroll
            for (int k = 0; k < 4; k++) acc[i][j][k] = 0.f;

    uint32_t asbase = (uint32_t)__cvta_generic_to_shared(As);
    uint32_t bsbase = (uint32_t)__cvta_generic_to_shared(Bs);
    // ldmatrix lane addressing
    int lr = lane & 7, lq = (lane >> 3) & 3;
    // A frags: row = r + (q&1)*8, col = (q>>1)*8
    uint32_t aoff0 = asbase + (((wm*32 + lr + (lq&1)*8) * APITCH + (lq>>1)*8) << 1);
    uint32_t aoff1 = aoff0 + ((16*APITCH) << 1);
    // B frags x4: row = r + (q>>1)*8, col = (q&1)*8
    uint32_t boff4 = bsbase + (((wn*24 + lr + (lq>>1)*8) * APITCH + (lq&1)*8) << 1);
    // B frag x2 (3rd n8): threads 0..15: row = wn*24+16+lr, col = (lane>>3)*8
    uint32_t boff2 = bsbase + (((wn*24 + 16 + lr) * APITCH + ((lane>>3)&1)*8) << 1);

    for (int kc = 0; kc < K; kc += 48) {
        // stage A tile: 128 rows x 48 cols (uint4 = 8 halves)
        {
            const uint4* src = reinterpret_cast<const uint4*>(A);
            #pragma unroll
            for (int it = 0; it < 3; it++) {
                int idx = tid + it*256;           // < 768
                int row = idx / 6, seg = idx - row*6;
                uint4 v = src[((size_t)(rowB + row) * K + kc + seg*8) >> 3];
                *reinterpret_cast<uint4*>(&As[row*APITCH + seg*8]) = v;
            }
            const uint4* wsrc = reinterpret_cast<const uint4*>(W);
            if (tid < 288 - 256 || tid < 288) { /* handled below */ }
            {
                int idx = tid;                     // 288 items, 256 threads
                if (idx < 288) {
                    int row = idx / 6, seg = idx - row*6;
                    uint4 v = wsrc[((size_t)(colB + row) * K + kc + seg*8) >> 3];
                    *reinterpret_cast<uint4*>(&Bs[row*APITCH + seg*8]) = v;
                }
                idx = tid + 256;
                if (idx < 288) {
                    int row = idx / 6, seg = idx - row*6;
                    uint4 v = wsrc[((size_t)(colB + row) * K + kc + seg*8) >> 3];
                    *reinterpret_cast<uint4*>(&Bs[row*APITCH + seg*8]) = v;
                }
            }
        }
        __syncthreads();
        #pragma unroll
        for (int kk = 0; kk < 48; kk += 16) {
            uint32_t a0[4], a1[4], b01[4], b2[2];
            ldsm_x4(a0, aoff0 + (kk << 1));
            ldsm_x4(a1, aoff1 + (kk << 1));
            ldsm_x4(b01, boff4 + (kk << 1));
            ldsm_x2(b2, boff2 + (kk << 1));
            mma_f16(acc[0][0], a0, b01[0], b01[1]);
            mma_f16(acc[0][1], a0, b01[2], b01[3]);
            mma_f16(acc[0][2], a0, b2[0],  b2[1]);
            mma_f16(acc[1][0], a1, b01[0], b01[1]);
            mma_f16(acc[1][1], a1, b01[2], b01[3]);
            mma_f16(acc[1][2], a1, b2[0],  b2[1]);
        }
        __syncthreads();
    }

    // epilogue
    #pragma unroll
    for (int mt = 0; mt < 2; mt++) {
        int r0 = rowB + wm*32 + mt*16 + g;
        int r1 = r0 + 8;
        #pragma unroll
        for (int nt = 0; nt < 3; nt++) {
            int cc = colB + wn*24 + nt*8 + 2*t;
            float v0 = acc[mt][nt][0], v1 = acc[mt][nt][1];
            float v2 = acc[mt][nt][2], v3 = acc[mt][nt][3];
            if (bias) {
                float b0 = bias[cc], b1 = bias[cc+1];
                v0 += b0; v1 += b1; v2 += b0; v3 += b1;
            }
            if (BOUT) {
                uint32_t* C = (uint32_t*)Cout;
                C[((size_t)r0 * Ncol + cc) >> 1] = packh2(v0, v1);
                C[((size_t)r1 * Ncol + cc) >> 1] = packh2(v2, v3);
            } else {
                // d-major fp32 out: C[col][row], resid same layout
                float* C = (float*)Cout;
                size_t i00 = (size_t)cc*MTOT + r0, i10 = i00 + MTOT;
                size_t i01 = (size_t)cc*MTOT + r1, i11 = i01 + MTOT;
                if (resid) { v0 += resid[i00]; v1 += resid[i10]; v2 += resid[i01]; v3 += resid[i11]; }
                C[i00] = v0; C[i10] = v1; C[i01] = v2; C[i11] = v3;
            }
        }
    }
}

// ---------------------------------------------------------------------------
// Attention v6: f16 flash attention, MUFU-halved via ex2.approx.f16x2,
// l computed by tensor core (ones column in V at d=18).
// K staged [NSEG][KPITCH=40] f16; V staged [NSEG][VPITCH=24] f16 (row-major).
// K frags: 2x ldmatrix.x4; V frags: 3x ldmatrix.x2.trans.
// ---------------------------------------------------------------------------
#define KPITCH 40
#define VPITCH 24
#define ATTN_SMEM_BYTES ((NSEG*KPITCH + NSEG*VPITCH) * 2)   // 131072

__global__ __launch_bounds__(512) void attn_kernel()
{
    int seg  = blockIdx.x;
    int b    = seg / (NHD * SFN);
    int rest = seg % (NHD * SFN);
    int hd   = rest / SFN;
    int sp   = rest % SFN;
    int base = b * NTOK + sp * NSEG;
    const int QKVROW = 3 * EE;

    extern __shared__ __half smh[];
    __half* Ks = smh;                       // [NSEG][KPITCH]
    __half* Vs = smh + NSEG * KPITCH;       // [NSEG][VPITCH]

    const uint32_t* qk32 = reinterpret_cast<const uint32_t*>(g_qkv_h);
    uint32_t* Ks32 = reinterpret_cast<uint32_t*>(Ks);
    uint32_t* Vs32 = reinterpret_cast<uint32_t*>(Vs);

    // stage K: rows padded 9 -> 20 u32 (zeros)
    for (int idx = threadIdx.x; idx < NSEG * (KPITCH/2); idx += 512) {
        int i = idx / (KPITCH/2), d2 = idx - i * (KPITCH/2);
        uint32_t v = 0u;
        if (d2 < 9)
            v = qk32[(((size_t)(base + i) * QKVROW + EE + hd * DHH) >> 1) + d2];
        Ks32[i * (KPITCH/2) + d2] = v;
    }
    // stage V: 12 u32/row: d2<9 data, d2==9 -> {1.0, 0} (l-ones at d=18), else 0
    for (int idx = threadIdx.x; idx < NSEG * (VPITCH/2); idx += 512) {
        int i = idx / (VPITCH/2), d2 = idx - i * (VPITCH/2);
        uint32_t v = 0u;
        if (d2 < 9)
            v = qk32[(((size_t)(base + i) * QKVROW + 2*EE + hd * DHH) >> 1) + d2];
        else if (d2 == 9)
            v = 0x00003C00u;                 // lo = 1.0h (d=18), hi = 0 (d=19)
        Vs32[i * (VPITCH/2) + d2] = v;
    }
    __syncthreads();

    int lane = threadIdx.x & 31, warp = threadIdx.x >> 5;
    int g = lane >> 2, t = lane & 3;
    int lr = lane & 7, lq = (lane >> 3) & 3;

    uint32_t ksb = (uint32_t)__cvta_generic_to_shared(Ks);
    uint32_t vsb = (uint32_t)__cvta_generic_to_shared(Vs);
    // K x4 lane addr: row = lr + (q>=2)*8, col = (q&1)*8
    uint32_t kaddr_base = ksb + (((lr + (lq>>1)*8) * KPITCH + (lq&1)*8) << 1);
    // V x2.trans lane addr (threads 0..15): row = lane&15
    uint32_t vaddr_base = vsb + (((lane & 15) * VPITCH) << 1);

    for (int qt = warp; qt < NSEG / 16; qt += 16) {
        int q0 = qt * 16;
        const uint32_t* q32a = qk32 + (((size_t)(base + q0 + g)     * QKVROW + hd * DHH) >> 1);
        const uint32_t* q32b = qk32 + (((size_t)(base + q0 + g + 8) * QKVROW + hd * DHH) >> 1);

        uint32_t qa[2][4];
        qa[0][0] = q32a[t];
        qa[0][1] = q32b[t];
        qa[0][2] = q32a[t + 4];
        qa[0][3] = q32b[t + 4];
        qa[1][0] = (t == 0) ? q32a[8] : 0u;
        qa[1][1] = (t == 0) ? q32b[8] : 0u;
        qa[1][2] = 0u; qa[1][3] = 0u;

        float o[3][4];
        #pragma unroll
        for (int dn = 0; dn < 3; dn++)
            #pragma unroll
            for (int i = 0; i < 4; i++) o[dn][i] = 0.f;

        uint32_t kaddr = kaddr_base;
        uint32_t vaddr = vaddr_base;
        for (int j0 = 0; j0 < NSEG; j0 += 16) {
            uint32_t kf0[4], kf1[4];
            ldsm_x4(kf0, kaddr);                       // kstep0: d0..15, both n-blocks
            ldsm_x4(kf1, kaddr + 32);                  // kstep1: d16..31
            float s0[4] = {0.f,0.f,0.f,0.f};
            float s1[4] = {0.f,0.f,0.f,0.f};
            mma_f16(s0, qa[0], kf0[0], kf0[1]);
            mma_f16(s1, qa[0], kf0[2], kf0[3]);
            mma_f16(s0, qa[1], kf1[0], kf1[1]);
            mma_f16(s1, qa[1], kf1[2], kf1[3]);

            uint32_t pa[4];
            pa[0] = ex2h2(cvth2(s0[0], s0[1]));
            pa[1] = ex2h2(cvth2(s0[2], s0[3]));
            pa[2] = ex2h2(cvth2(s1[0], s1[1]));
            pa[3] = ex2h2(cvth2(s1[2], s1[3]));

            uint32_t vf[2];
            ldsm_x2t(vf, vaddr);                       // d 0..7
            mma_f16(o[0], pa, vf[0], vf[1]);
            ldsm_x2t(vf, vaddr + 16);                  // d 8..15
            mma_f16(o[1], pa, vf[0], vf[1]);
            ldsm_x2t(vf, vaddr + 32);                  // d 16..23 (incl. ones at 18)
            mma_f16(o[2], pa, vf[0], vf[1]);

            kaddr += 16 * KPITCH * 2;
            vaddr += 16 * VPITCH * 2;
        }

        // l lives in o[2][0] (row g) and o[2][2] (row g+8) of lanes with t==1
        int srcl = (lane & 28) | 1;
        float lg  = __shfl_sync(0xffffffffu, o[2][0], srcl);
        float lg8 = __shfl_sync(0xffffffffu, o[2][2], srcl);
        float ig = 1.f / lg, ig8 = 1.f / lg8;

        uint32_t* o32 = reinterpret_cast<uint32_t*>(g_o_h);
        #pragma unroll
        for (int dn = 0; dn < 3; dn++) {
            int dc = dn * 8 + 2 * t;
            if (dc < DHH) {
                o32[((size_t)(base + q0 + g)     * EE + hd*DHH + dc) >> 1] = packh2(o[dn][0]*ig,  o[dn][1]*ig);
                o32[((size_t)(base + q0 + g + 8) * EE + hd*DHH + dc) >> 1] = packh2(o[dn][2]*ig8, o[dn][3]*ig8);
            }
        }
    }
}

// ---------------------------------------------------------------------------
// Fold (gather, d-major cols -> fully coalesced)
// ---------------------------------------------------------------------------
__global__ void fold_kernel()
{
    int idx = blockIdx.x * blockDim.x + threadIdx.x;
    if (idx >= BB*CC*HH*WW) return;
    int w = idx & 63;
    int h = (idx >> 6) & 63;
    int c = (idx >> 12) & 31;
    int b =  idx >> 17;
    float sum = 0.f;
    #pragma unroll
    for (int i = 0; i < 3; i++) {
        int hh = h + 1 - i;
        if (hh < 0 || hh >= HH) continue;
        #pragma unroll
        for (int j = 0; j < 3; j++) {
            int ww = w + 1 - j;
            if (ww < 0 || ww >= WW) continue;
            sum += g_cols[(size_t)(c*9 + i*3 + j)*MTOT + b*NTOK + hh*WW + ww];
        }
    }
    g_t[idx] = sum;
}

// ---------------------------------------------------------------------------
// Final: out = x + elu(conv3x3(t) + conv_b)
// ---------------------------------------------------------------------------
__global__ void conv_elu_kernel(const float* __restrict__ x,
                                const float* __restrict__ cw,
                                const float* __restrict__ cb,
                                float* __restrict__ out)
{
    int idx = blockIdx.x * blockDim.x + threadIdx.x;
    if (idx >= BB*CC*HH*WW) return;
    int w  = idx & 63;
    int h  = (idx >> 6) & 63;
    int co = (idx >> 12) & 31;
    int b  =  idx >> 17;

    float sum = cb[co];
    for (int ci = 0; ci < CC; ci++) {
        const float* tplane = &g_t[((size_t)(b*CC + ci))*HH*WW];
        const float* wk = &cw[((size_t)(co*CC + ci))*9];
        #pragma unroll
        for (int kh = 0; kh < 3; kh++) {
            int hh = h + kh - 1;
            if (hh < 0 || hh >= HH) continue;
            #pragma unroll
            for (int kw = 0; kw < 3; kw++) {
                int ww = w + kw - 1;
                if (ww < 0 || ww >= WW) continue;
                sum = fmaf(tplane[hh*WW + ww], wk[kh*3 + kw], sum);
            }
        }
    }
    float e = sum > 0.f ? sum : expm1f(sum);
    out[idx] = x[idx] + e;
}

// ---------------------------------------------------------------------------
// Launch
// ---------------------------------------------------------------------------
extern "C" void kernel_launch(void* const* d_in, const int* in_sizes, int n_in,
                              void* d_out, int out_size)
{
    (void)in_sizes; (void)n_in; (void)out_size;
    const float* x     = (const float*)d_in[0];
    const float* ln_g  = (const float*)d_in[1];
    const float* ln_b  = (const float*)d_in[2];
    const float* convw = (const float*)d_in[3];
    const float* convb = (const float*)d_in[4];
    float* out = (float*)d_out;

    float *p_t, *p_cols;
    __half *p_colsn, *p_xr, *p_qkv, *p_o, *p_w;
    cudaGetSymbolAddress((void**)&p_t,     g_t);
    cudaGetSymbolAddress((void**)&p_cols,  g_cols);
    cudaGetSymbolAddress((void**)&p_colsn, g_colsn_h);
    cudaGetSymbolAddress((void**)&p_xr,    g_xr_h);
    cudaGetSymbolAddress((void**)&p_qkv,   g_qkv_h);
    cudaGetSymbolAddress((void**)&p_o,     g_o_h);
    cudaGetSymbolAddress((void**)&p_w,     g_w_h);

    cudaFuncSetAttribute(attn_kernel, cudaFuncAttributeMaxDynamicSharedMemorySize, ATTN_SMEM_BYTES);

    const int NPIX = BB*CC*HH*WW;

    for (int L = 0; L < 3; L++) {
        wconv_kernel<<<(WL_STRIDE + 255)/256, 256>>>(
            (const float*)d_in[5 + 5*L + 0],
            (const float*)d_in[5 + 5*L + 2],
            (const float*)d_in[5 + 5*L + 3],
            p_w + (size_t)L * WL_STRIDE);
    }

    for (int L = 0; L < 3; L++) {
        const float* br = (const float*)d_in[5 + 5*L + 1];
        const float* be = (const float*)d_in[5 + 5*L + 4];
        const __half* wr   = p_w + (size_t)L * WL_STRIDE;
        const __half* wqkv = wr + WQKV_OFF;
        const __half* we   = wr + WE_OFF;
        const float* img = (L == 0) ? x : p_t;

        unfold_ln_kernel<<<MTOT/32, 256>>>(img, ln_g, ln_b);
        // xr = colsn @ wr^T + br   (f16 out, tok-major)
        gemm_h_kernel<288, true><<<dim3(EE/48, MTOT/128), 256>>>(
            p_colsn, wr, br, nullptr, p_xr, EE);
        // qkv = xr @ wqkv^T        (f16 out, Q pre-scaled)
        gemm_h_kernel<144, true><<<dim3(3*EE/48, MTOT/128), 256>>>(
            p_xr, wqkv, nullptr, nullptr, p_qkv, 3*EE);
        attn_kernel<<<BB*NHD*SFN, 512, ATTN_SMEM_BYTES>>>();
        // cols += o @ we^T + be    (fp32 d-major out + residual)
        gemm_h_kernel<144, false><<<dim3(DD/48, MTOT/128), 256>>>(
            p_o, we, be, p_cols, p_cols, DD);
        fold_kernel<<<(NPIX + 255)/256, 256>>>();
    }
    conv_elu_kernel<<<(NPIX + 255)/256, 256>>>(x, convw, convb, out);
}

// round 8
// speedup vs baseline: 4.4189x; 1.1463x over previous
#include <cuda_runtime.h>
#include <cuda_fp16.h>
#include <math.h>
#include <stdint.h>

// Problem constants
#define BB   4
#define CC   32
#define HH   64
#define WW   64
#define DD   288          // C*K*K
#define EE   144          // D/2
#define NHD  8            // heads
#define DHH  18           // head dim
#define SFN  4            // split factor
#define NTOK 4096         // H*W tokens per batch
#define NSEG 1024         // NTOK / SF
#define MTOT (BB*NTOK)    // 16384 tokens total

// weight buffer layout (f16), per layer
#define WR_ELEMS   (EE*DD)
#define WQKV_ELEMS (3*EE*EE)
#define WE_ELEMS   (DD*EE)
#define WL_STRIDE  (WR_ELEMS + WQKV_ELEMS + WE_ELEMS)
#define WQKV_OFF   WR_ELEMS
#define WE_OFF     (WR_ELEMS + WQKV_ELEMS)

// ---- f16 mma / ldmatrix helpers --------------------------------------------
__device__ __forceinline__ void mma_f16(float* c, const uint32_t* a, uint32_t b0, uint32_t b1) {
    asm("mma.sync.aligned.m16n8k16.row.col.f32.f16.f16.f32 "
        "{%0,%1,%2,%3},{%4,%5,%6,%7},{%8,%9},{%0,%1,%2,%3};"
        : "+f"(c[0]), "+f"(c[1]), "+f"(c[2]), "+f"(c[3])
        : "r"(a[0]), "r"(a[1]), "r"(a[2]), "r"(a[3]), "r"(b0), "r"(b1));
}
__device__ __forceinline__ void ldsm_x4(uint32_t* r, uint32_t addr) {
    asm volatile("ldmatrix.sync.aligned.m8n8.x4.shared.b16 {%0,%1,%2,%3},[%4];"
        : "=r"(r[0]), "=r"(r[1]), "=r"(r[2]), "=r"(r[3]) : "r"(addr));
}
__device__ __forceinline__ void ldsm_x2(uint32_t* r, uint32_t addr) {
    asm volatile("ldmatrix.sync.aligned.m8n8.x2.shared.b16 {%0,%1},[%2];"
        : "=r"(r[0]), "=r"(r[1]) : "r"(addr));
}
__device__ __forceinline__ void ldsm_x2t(uint32_t* r, uint32_t addr) {
    asm volatile("ldmatrix.sync.aligned.m8n8.x2.trans.shared.b16 {%0,%1},[%2];"
        : "=r"(r[0]), "=r"(r[1]) : "r"(addr));
}
__device__ __forceinline__ uint32_t cvth2(float lo, float hi) {
    uint32_t r; asm("cvt.rn.f16x2.f32 %0,%1,%2;" : "=r"(r) : "f"(hi), "f"(lo)); return r;
}
__device__ __forceinline__ uint32_t ex2h2(uint32_t x) {
    uint32_t r; asm("ex2.approx.f16x2 %0,%1;" : "=r"(r) : "r"(x)); return r;
}
__device__ __forceinline__ uint32_t packh2(float lo, float hi) {
    __half2 h = __floats2half2_rn(lo, hi);
    return *reinterpret_cast<uint32_t*>(&h);
}

// Scratch (device globals: allocation-free rule)
__device__ float  g_t[BB*CC*HH*WW];        // current image (fp32)
__device__ float  g_br[DD*MTOT];           // EMHA branch output, fp32 D-MAJOR [d][tok]
__device__ __half g_colsn_h[MTOT*DD];      // layernormed cols (f16, tok-major)
__device__ __half g_xr_h[MTOT*EE];         // reduced tokens (f16)
__device__ __half g_qkv_h[MTOT*3*EE];      // qkv (f16, Q pre-scaled)
__device__ __half g_o_h[MTOT*EE];          // attention output (f16)
__device__ __half g_w_h[3*WL_STRIDE];      // converted weights, 3 layers

// ---------------------------------------------------------------------------
// Weight conversion fp32 -> f16; Q-rows of wqkv pre-scaled by 18^-0.5*log2(e).
// ---------------------------------------------------------------------------
__global__ void wconv_kernel(const float* __restrict__ wr,
                             const float* __restrict__ wqkv,
                             const float* __restrict__ we,
                             __half* __restrict__ dst)
{
    const float qs = 0.235702260395515841f * 1.4426950408889634f;
    int i = blockIdx.x * 256 + threadIdx.x;
    if (i >= WL_STRIDE) return;
    float v;
    if (i < WR_ELEMS) v = wr[i];
    else if (i < WE_OFF) {
        int j = i - WQKV_OFF;
        v = wqkv[j];
        if (j < EE * EE) v *= qs;
    } else v = we[i - WE_OFF];
    dst[i] = __float2half(v);
}

// ---------------------------------------------------------------------------
// Fused unfold + LayerNorm. One WARP per token; f16 normalized output ONLY
// (the fp32 residual stream is algebraically eliminated: fold∘unfold = m·t).
// ---------------------------------------------------------------------------
__global__ __launch_bounds__(256) void unfold_ln_kernel(
    const float* __restrict__ img,
    const float* __restrict__ lng,
    const float* __restrict__ lnb)
{
    int warp = threadIdx.x >> 5, lane = threadIdx.x & 31;
    int tok = blockIdx.x * 8 + warp;
    int b = tok >> 12;
    int n = tok & (NTOK - 1);
    int h = n >> 6, w = n & 63;

    float v[9];
    float s = 0.f, q = 0.f;
    #pragma unroll
    for (int i = 0; i < 9; i++) {
        int d = i * 32 + lane;
        int c  = d / 9;
        int r  = d - c * 9;
        int kh = r / 3, kw = r - kh * 3;
        int hh = h + kh - 1, ww = w + kw - 1;
        float x = 0.f;
        if (hh >= 0 && hh < HH && ww >= 0 && ww < WW)
            x = img[((b*CC + c)*HH + hh)*WW + ww];
        v[i] = x; s += x; q = fmaf(x, x, q);
    }
    #pragma unroll
    for (int o = 16; o > 0; o >>= 1) {
        s += __shfl_xor_sync(0xffffffffu, s, o);
        q += __shfl_xor_sync(0xffffffffu, q, o);
    }
    float mu = s * (1.f / DD);
    float rstd = rsqrtf(q * (1.f / DD) - mu * mu + 1e-5f);
    #pragma unroll
    for (int i = 0; i < 9; i++) {
        int d = i * 32 + lane;
        g_colsn_h[(size_t)tok*DD + d] =
            __float2half((v[i] - mu) * rstd * __ldg(&lng[d]) + __ldg(&lnb[d]));
    }
}

// ---------------------------------------------------------------------------
// f16 GEMM, smem-staged + ldmatrix: C(M,N) = A(M,K)*W(N,K)^T (+bias)
// CTA 256 thr = 8 warps (4M x 2N); CTA tile 128x48; warp tile 32x24; k-chunk 48.
// BOUT=true: f16 packed tok-major out. BOUT=false: fp32 D-MAJOR out.
// ---------------------------------------------------------------------------
#define APITCH 56
template<int K, bool BOUT>
__global__ __launch_bounds__(256) void gemm_h_kernel(
    const __half* __restrict__ A, const __half* __restrict__ W,
    const float* __restrict__ bias,
    void* __restrict__ Cout, int Ncol)
{
    __shared__ __half As[128*APITCH];
    __shared__ __half Bs[48*APITCH];

    int tid = threadIdx.x;
    int warp = tid >> 5, lane = tid & 31;
    int g = lane >> 2, t = lane & 3;
    int wm = warp & 3, wn = warp >> 2;
    int rowB = blockIdx.y * 128;
    int colB = blockIdx.x * 48;

    float acc[2][3][4];
    #pragma unroll
    for (int i = 0; i < 2; i++)
        #pragma unroll
        for (int j = 0; j < 3; j++)
            #pragma unroll
            for (int k = 0; k < 4; k++) acc[i][j][k] = 0.f;

    uint32_t asbase = (uint32_t)__cvta_generic_to_shared(As);
    uint32_t bsbase = (uint32_t)__cvta_generic_to_shared(Bs);
    int lr = lane & 7, lq = (lane >> 3) & 3;
    uint32_t aoff0 = asbase + (((wm*32 + lr + (lq&1)*8) * APITCH + (lq>>1)*8) << 1);
    uint32_t aoff1 = aoff0 + ((16*APITCH) << 1);
    uint32_t boff4 = bsbase + (((wn*24 + lr + (lq>>1)*8) * APITCH + (lq&1)*8) << 1);
    uint32_t boff2 = bsbase + (((wn*24 + 16 + lr) * APITCH + ((lane>>3)&1)*8) << 1);

    for (int kc = 0; kc < K; kc += 48) {
        {
            const uint4* src = reinterpret_cast<const uint4*>(A);
            #pragma unroll
            for (int it = 0; it < 3; it++) {
                int idx = tid + it*256;
                int row = idx / 6, seg = idx - row*6;
                uint4 v = src[((size_t)(rowB + row) * K + kc + seg*8) >> 3];
                *reinterpret_cast<uint4*>(&As[row*APITCH + seg*8]) = v;
            }
            const uint4* wsrc = reinterpret_cast<const uint4*>(W);
            {
                int idx = tid;
                if (idx < 288) {
                    int row = idx / 6, seg = idx - row*6;
                    uint4 v = wsrc[((size_t)(colB + row) * K + kc + seg*8) >> 3];
                    *reinterpret_cast<uint4*>(&Bs[row*APITCH + seg*8]) = v;
                }
                idx = tid + 256;
                if (idx < 288) {
                    int row = idx / 6, seg = idx - row*6;
                    uint4 v = wsrc[((size_t)(colB + row) * K + kc + seg*8) >> 3];
                    *reinterpret_cast<uint4*>(&Bs[row*APITCH + seg*8]) = v;
                }
            }
        }
        __syncthreads();
        #pragma unroll
        for (int kk = 0; kk < 48; kk += 16) {
            uint32_t a0[4], a1[4], b01[4], b2[2];
            ldsm_x4(a0, aoff0 + (kk << 1));
            ldsm_x4(a1, aoff1 + (kk << 1));
            ldsm_x4(b01, boff4 + (kk << 1));
            ldsm_x2(b2, boff2 + (kk << 1));
            mma_f16(acc[0][0], a0, b01[0], b01[1]);
            mma_f16(acc[0][1], a0, b01[2], b01[3]);
            mma_f16(acc[0][2], a0, b2[0],  b2[1]);
            mma_f16(acc[1][0], a1, b01[0], b01[1]);
            mma_f16(acc[1][1], a1, b01[2], b01[3]);
            mma_f16(acc[1][2], a1, b2[0],  b2[1]);
        }
        __syncthreads();
    }

    #pragma unroll
    for (int mt = 0; mt < 2; mt++) {
        int r0 = rowB + wm*32 + mt*16 + g;
        int r1 = r0 + 8;
        #pragma unroll
        for (int nt = 0; nt < 3; nt++) {
            int cc = colB + wn*24 + nt*8 + 2*t;
            float v0 = acc[mt][nt][0], v1 = acc[mt][nt][1];
            float v2 = acc[mt][nt][2], v3 = acc[mt][nt][3];
            if (bias) {
                float b0 = bias[cc], b1 = bias[cc+1];
                v0 += b0; v1 += b1; v2 += b0; v3 += b1;
            }
            if (BOUT) {
                uint32_t* C = (uint32_t*)Cout;
                C[((size_t)r0 * Ncol + cc) >> 1] = packh2(v0, v1);
                C[((size_t)r1 * Ncol + cc) >> 1] = packh2(v2, v3);
            } else {
                float* C = (float*)Cout;
                size_t i00 = (size_t)cc*MTOT + r0, i10 = i00 + MTOT;
                size_t i01 = (size_t)cc*MTOT + r1, i11 = i01 + MTOT;
                C[i00] = v0; C[i10] = v1; C[i01] = v2; C[i11] = v3;
            }
        }
    }
}

// ---------------------------------------------------------------------------
// Attention: f16 flash, ex2.approx.f16x2, l via ones-column in V (d=18).
// ---------------------------------------------------------------------------
#define KPITCH 40
#define VPITCH 24
#define ATTN_SMEM_BYTES ((NSEG*KPITCH + NSEG*VPITCH) * 2)   // 131072

__global__ __launch_bounds__(512) void attn_kernel()
{
    int seg  = blockIdx.x;
    int b    = seg / (NHD * SFN);
    int rest = seg % (NHD * SFN);
    int hd   = rest / SFN;
    int sp   = rest % SFN;
    int base = b * NTOK + sp * NSEG;
    const int QKVROW = 3 * EE;

    extern __shared__ __half smh[];
    __half* Ks = smh;                       // [NSEG][KPITCH]
    __half* Vs = smh + NSEG * KPITCH;       // [NSEG][VPITCH]

    const uint32_t* qk32 = reinterpret_cast<const uint32_t*>(g_qkv_h);
    uint32_t* Ks32 = reinterpret_cast<uint32_t*>(Ks);
    uint32_t* Vs32 = reinterpret_cast<uint32_t*>(Vs);

    for (int idx = threadIdx.x; idx < NSEG * (KPITCH/2); idx += 512) {
        int i = idx / (KPITCH/2), d2 = idx - i * (KPITCH/2);
        uint32_t v = 0u;
        if (d2 < 9)
            v = qk32[(((size_t)(base + i) * QKVROW + EE + hd * DHH) >> 1) + d2];
        Ks32[i * (KPITCH/2) + d2] = v;
    }
    for (int idx = threadIdx.x; idx < NSEG * (VPITCH/2); idx += 512) {
        int i = idx / (VPITCH/2), d2 = idx - i * (VPITCH/2);
        uint32_t v = 0u;
        if (d2 < 9)
            v = qk32[(((size_t)(base + i) * QKVROW + 2*EE + hd * DHH) >> 1) + d2];
        else if (d2 == 9)
            v = 0x00003C00u;                 // {1.0h, 0} -> l-ones at d=18
        Vs32[i * (VPITCH/2) + d2] = v;
    }
    __syncthreads();

    int lane = threadIdx.x & 31, warp = threadIdx.x >> 5;
    int g = lane >> 2, t = lane & 3;
    int lr = lane & 7, lq = (lane >> 3) & 3;

    uint32_t ksb = (uint32_t)__cvta_generic_to_shared(Ks);
    uint32_t vsb = (uint32_t)__cvta_generic_to_shared(Vs);
    uint32_t kaddr_base = ksb + (((lr + (lq>>1)*8) * KPITCH + (lq&1)*8) << 1);
    uint32_t vaddr_base = vsb + (((lane & 15) * VPITCH) << 1);

    for (int qt = warp; qt < NSEG / 16; qt += 16) {
        int q0 = qt * 16;
        const uint32_t* q32a = qk32 + (((size_t)(base + q0 + g)     * QKVROW + hd * DHH) >> 1);
        const uint32_t* q32b = qk32 + (((size_t)(base + q0 + g + 8) * QKVROW + hd * DHH) >> 1);

        uint32_t qa[2][4];
        qa[0][0] = q32a[t];
        qa[0][1] = q32b[t];
        qa[0][2] = q32a[t + 4];
        qa[0][3] = q32b[t + 4];
        qa[1][0] = (t == 0) ? q32a[8] : 0u;
        qa[1][1] = (t == 0) ? q32b[8] : 0u;
        qa[1][2] = 0u; qa[1][3] = 0u;

        float o[3][4];
        #pragma unroll
        for (int dn = 0; dn < 3; dn++)
            #pragma unroll
            for (int i = 0; i < 4; i++) o[dn][i] = 0.f;

        uint32_t kaddr = kaddr_base;
        uint32_t vaddr = vaddr_base;
        for (int j0 = 0; j0 < NSEG; j0 += 16) {
            uint32_t kf0[4], kf1[4];
            ldsm_x4(kf0, kaddr);
            ldsm_x4(kf1, kaddr + 32);
            float s0[4] = {0.f,0.f,0.f,0.f};
            float s1[4] = {0.f,0.f,0.f,0.f};
            mma_f16(s0, qa[0], kf0[0], kf0[1]);
            mma_f16(s1, qa[0], kf0[2], kf0[3]);
            mma_f16(s0, qa[1], kf1[0], kf1[1]);
            mma_f16(s1, qa[1], kf1[2], kf1[3]);

            uint32_t pa[4];
            pa[0] = ex2h2(cvth2(s0[0], s0[1]));
            pa[1] = ex2h2(cvth2(s0[2], s0[3]));
            pa[2] = ex2h2(cvth2(s1[0], s1[1]));
            pa[3] = ex2h2(cvth2(s1[2], s1[3]));

            uint32_t vf[2];
            ldsm_x2t(vf, vaddr);
            mma_f16(o[0], pa, vf[0], vf[1]);
            ldsm_x2t(vf, vaddr + 16);
            mma_f16(o[1], pa, vf[0], vf[1]);
            ldsm_x2t(vf, vaddr + 32);
            mma_f16(o[2], pa, vf[0], vf[1]);

            kaddr += 16 * KPITCH * 2;
            vaddr += 16 * VPITCH * 2;
        }

        int srcl = (lane & 28) | 1;
        float lg  = __shfl_sync(0xffffffffu, o[2][0], srcl);
        float lg8 = __shfl_sync(0xffffffffu, o[2][2], srcl);
        float ig = 1.f / lg, ig8 = 1.f / lg8;

        uint32_t* o32 = reinterpret_cast<uint32_t*>(g_o_h);
        #pragma unroll
        for (int dn = 0; dn < 3; dn++) {
            int dc = dn * 8 + 2 * t;
            if (dc < DHH) {
                o32[((size_t)(base + q0 + g)     * EE + hd*DHH + dc) >> 1] = packh2(o[dn][0]*ig,  o[dn][1]*ig);
                o32[((size_t)(base + q0 + g + 8) * EE + hd*DHH + dc) >> 1] = packh2(o[dn][2]*ig8, o[dn][3]*ig8);
            }
        }
    }
}

// ---------------------------------------------------------------------------
// Fold v2: t_next = m(h)·m(w)·t + gather(branch).  (fold∘unfold = diag(m))
// ---------------------------------------------------------------------------
__global__ void fold_kernel(const float* __restrict__ img)
{
    int idx = blockIdx.x * blockDim.x + threadIdx.x;
    if (idx >= BB*CC*HH*WW) return;
    int w = idx & 63;
    int h = (idx >> 6) & 63;
    int c = (idx >> 12) & 31;
    int b =  idx >> 17;

    float mh = (h == 0 || h == HH-1) ? 2.f : 3.f;
    float mw = (w == 0 || w == WW-1) ? 2.f : 3.f;
    float sum = img[idx] * (mh * mw);

    #pragma unroll
    for (int i = 0; i < 3; i++) {
        int hh = h + 1 - i;
        if (hh < 0 || hh >= HH) continue;
        #pragma unroll
        for (int j = 0; j < 3; j++) {
            int ww = w + 1 - j;
            if (ww < 0 || ww >= WW) continue;
            sum += g_br[(size_t)(c*9 + i*3 + j)*MTOT + b*NTOK + hh*WW + ww];
        }
    }
    g_t[idx] = sum;
}

// ---------------------------------------------------------------------------
// Final: out = x + elu(conv3x3(t) + conv_b)
// ---------------------------------------------------------------------------
__global__ void conv_elu_kernel(const float* __restrict__ x,
                                const float* __restrict__ cw,
                                const float* __restrict__ cb,
                                float* __restrict__ out)
{
    int idx = blockIdx.x * blockDim.x + threadIdx.x;
    if (idx >= BB*CC*HH*WW) return;
    int w  = idx & 63;
    int h  = (idx >> 6) & 63;
    int co = (idx >> 12) & 31;
    int b  =  idx >> 17;

    float sum = cb[co];
    for (int ci = 0; ci < CC; ci++) {
        const float* tplane = &g_t[((size_t)(b*CC + ci))*HH*WW];
        const float* wk = &cw[((size_t)(co*CC + ci))*9];
        #pragma unroll
        for (int kh = 0; kh < 3; kh++) {
            int hh = h + kh - 1;
            if (hh < 0 || hh >= HH) continue;
            #pragma unroll
            for (int kw = 0; kw < 3; kw++) {
                int ww = w + kw - 1;
                if (ww < 0 || ww >= WW) continue;
                sum = fmaf(tplane[hh*WW + ww], wk[kh*3 + kw], sum);
            }
        }
    }
    float e = sum > 0.f ? sum : expm1f(sum);
    out[idx] = x[idx] + e;
}

// ---------------------------------------------------------------------------
// Launch
// ---------------------------------------------------------------------------
extern "C" void kernel_launch(void* const* d_in, const int* in_sizes, int n_in,
                              void* d_out, int out_size)
{
    (void)in_sizes; (void)n_in; (void)out_size;
    const float* x     = (const float*)d_in[0];
    const float* ln_g  = (const float*)d_in[1];
    const float* ln_b  = (const float*)d_in[2];
    const float* convw = (const float*)d_in[3];
    const float* convb = (const float*)d_in[4];
    float* out = (float*)d_out;

    float *p_t, *p_br;
    __half *p_colsn, *p_xr, *p_qkv, *p_o, *p_w;
    cudaGetSymbolAddress((void**)&p_t,     g_t);
    cudaGetSymbolAddress((void**)&p_br,    g_br);
    cudaGetSymbolAddress((void**)&p_colsn, g_colsn_h);
    cudaGetSymbolAddress((void**)&p_xr,    g_xr_h);
    cudaGetSymbolAddress((void**)&p_qkv,   g_qkv_h);
    cudaGetSymbolAddress((void**)&p_o,     g_o_h);
    cudaGetSymbolAddress((void**)&p_w,     g_w_h);

    cudaFuncSetAttribute(attn_kernel, cudaFuncAttributeMaxDynamicSharedMemorySize, ATTN_SMEM_BYTES);

    const int NPIX = BB*CC*HH*WW;

    for (int L = 0; L < 3; L++) {
        wconv_kernel<<<(WL_STRIDE + 255)/256, 256>>>(
            (const float*)d_in[5 + 5*L + 0],
            (const float*)d_in[5 + 5*L + 2],
            (const float*)d_in[5 + 5*L + 3],
            p_w + (size_t)L * WL_STRIDE);
    }

    for (int L = 0; L < 3; L++) {
        const float* br = (const float*)d_in[5 + 5*L + 1];
        const float* be = (const float*)d_in[5 + 5*L + 4];
        const __half* wr   = p_w + (size_t)L * WL_STRIDE;
        const __half* wqkv = wr + WQKV_OFF;
        const __half* we   = wr + WE_OFF;
        const float* img = (L == 0) ? x : p_t;

        unfold_ln_kernel<<<MTOT/8, 256>>>(img, ln_g, ln_b);
        // xr = colsn @ wr^T + br   (f16 out, tok-major)
        gemm_h_kernel<288, true><<<dim3(EE/48, MTOT/128), 256>>>(
            p_colsn, wr, br, p_xr, EE);
        // qkv = xr @ wqkv^T        (f16 out, Q pre-scaled)
        gemm_h_kernel<144, true><<<dim3(3*EE/48, MTOT/128), 256>>>(
            p_xr, wqkv, nullptr, p_qkv, 3*EE);
        attn_kernel<<<BB*NHD*SFN, 512, ATTN_SMEM_BYTES>>>();
        // branch = o @ we^T + be   (fp32 d-major out, NO residual)
        gemm_h_kernel<144, false><<<dim3(DD/48, MTOT/128), 256>>>(
            p_o, we, be, p_br, DD);
        // t = m·t + fold(branch)
        fold_kernel<<<(NPIX + 255)/256, 256>>>(img);
    }
    conv_elu_kernel<<<(NPIX + 255)/256, 256>>>(x, convw, convb, out);
}